// round 13
// baseline (speedup 1.0000x reference)
#include <cuda_runtime.h>
#include <cstdint>

#define BB 8
#define LL 2048
#define DD 256
#define BM 64
#define BN 64
#define NT (LL / BN)

// ---- global scratch (allocation-free device arrays) ----
__device__ float    g_yf[(size_t)BB * LL * DD];     // tf32(x*wp)
__device__ float    g_h [(size_t)BB * LL * 512];    // [tf32(x) | tf32(attn)]
__device__ uint32_t g_xT[(size_t)BB * 256 * 1024];  // x^T bf16 j-pairs
__device__ float    g_su[(size_t)BB * LL];
__device__ float    g_wtf[3 * 256 * 512];           // W^T tf32 [m][n][k]

// ---- helpers ----
__device__ __forceinline__ uint32_t smem_u32(const void* p) {
    uint32_t a;
    asm("{ .reg .u64 t; cvta.to.shared.u64 t, %1; cvt.u32.u64 %0, t; }" : "=r"(a) : "l"(p));
    return a;
}
__device__ __forceinline__ uint32_t pk(float lo, float hi) {
    uint32_t r; asm("cvt.rn.bf16x2.f32 %0, %1, %2;" : "=r"(r) : "f"(hi), "f"(lo)); return r;
}
__device__ __forceinline__ float f2tf(float f) {
    uint32_t u; asm("cvt.rna.tf32.f32 %0, %1;" : "=r"(u) : "f"(f)); return __uint_as_float(u);
}
__device__ __forceinline__ void cpa16(uint32_t dst, const void* src) {
    asm volatile("cp.async.ca.shared.global [%0], [%1], 16;" :: "r"(dst), "l"(src));
}
#define CP_COMMIT() asm volatile("cp.async.commit_group;")
#define CP_WAIT0()  asm volatile("cp.async.wait_group 0;")
#define PROD_BAR()  asm volatile("bar.sync 1, 128;" ::: "memory")

__device__ __forceinline__ void ldsm4(uint32_t* r, uint32_t addr) {
    asm volatile("ldmatrix.sync.aligned.m8n8.x4.shared.b16 {%0,%1,%2,%3}, [%4];"
        : "=r"(r[0]), "=r"(r[1]), "=r"(r[2]), "=r"(r[3]) : "r"(addr));
}
__device__ __forceinline__ void mma_bf16(float* c, const uint32_t* a, const uint32_t* b) {
    asm volatile("mma.sync.aligned.m16n8k16.row.col.f32.bf16.bf16.f32 "
        "{%0,%1,%2,%3}, {%4,%5,%6,%7}, {%8,%9}, {%0,%1,%2,%3};"
        : "+f"(c[0]), "+f"(c[1]), "+f"(c[2]), "+f"(c[3])
        : "r"(a[0]), "r"(a[1]), "r"(a[2]), "r"(a[3]), "r"(b[0]), "r"(b[1]));
}
__device__ __forceinline__ void mma_tf32(float* c, const uint32_t* a, const uint32_t* b) {
    asm volatile("mma.sync.aligned.m16n8k8.row.col.f32.tf32.tf32.f32 "
        "{%0,%1,%2,%3}, {%4,%5,%6,%7}, {%8,%9}, {%0,%1,%2,%3};"
        : "+f"(c[0]), "+f"(c[1]), "+f"(c[2]), "+f"(c[3])
        : "r"(a[0]), "r"(a[1]), "r"(a[2]), "r"(a[3]), "r"(b[0]), "r"(b[1]));
}

// ===========================================================================
// prep kernels (unchanged)
// ===========================================================================
__global__ void prep_su(const float* __restrict__ x, const float* __restrict__ w_itr) {
    int row = blockIdx.x * 8 + (threadIdx.x >> 5);
    int lane = threadIdx.x & 31;
    const float* xr = x + (size_t)row * DD;
    float s = 0.f;
    #pragma unroll
    for (int k = 0; k < 8; k++) s += xr[lane + 32 * k] * w_itr[lane + 32 * k];
    #pragma unroll
    for (int off = 16; off > 0; off >>= 1) s += __shfl_xor_sync(0xffffffffu, s, off);
    if (lane == 0) g_su[row] = s;
}

__global__ void prep_pack(const float* __restrict__ x, const float* __restrict__ w_itr) {
    __shared__ float tl[64][65];
    int blk = blockIdx.x;                      // b*128 + jt*4 + dt
    int b = blk >> 7, rem = blk & 127, jt = rem >> 2, dt = rem & 3;
    int j0 = jt * 64, d0 = dt * 64;
    const float* xb = x + ((size_t)b * LL + j0) * DD + d0;
    int tid = threadIdx.x;
    #pragma unroll
    for (int p = 0; p < 4; p++) {
        int idx = tid + p * 256;
        int r = idx >> 4, c4 = idx & 15;
        float4 v = *(const float4*)(xb + (size_t)r * DD + c4 * 4);
        tl[r][c4 * 4 + 0] = v.x; tl[r][c4 * 4 + 1] = v.y;
        tl[r][c4 * 4 + 2] = v.z; tl[r][c4 * 4 + 3] = v.w;
    }
    __syncthreads();
    const float* wp = w_itr + 2 * DD;
    #pragma unroll
    for (int p = 0; p < 4; p++) {
        int idx = tid + p * 256;
        int r = idx >> 4, c4 = idx & 15;
        float a0 = tl[r][c4 * 4 + 0], a1 = tl[r][c4 * 4 + 1];
        float a2 = tl[r][c4 * 4 + 2], a3 = tl[r][c4 * 4 + 3];
        float4 y, h;
        y.x = f2tf(a0 * wp[d0 + c4 * 4 + 0]); y.y = f2tf(a1 * wp[d0 + c4 * 4 + 1]);
        y.z = f2tf(a2 * wp[d0 + c4 * 4 + 2]); y.w = f2tf(a3 * wp[d0 + c4 * 4 + 3]);
        h.x = f2tf(a0); h.y = f2tf(a1); h.z = f2tf(a2); h.w = f2tf(a3);
        *(float4*)(g_yf + ((size_t)b * LL + j0 + r) * DD + d0 + c4 * 4) = y;
        *(float4*)(g_h  + ((size_t)b * LL + j0 + r) * 512 + d0 + c4 * 4) = h;
    }
    #pragma unroll
    for (int p = 0; p < 8; p++) {
        int idx = tid + p * 256;
        int dl = idx >> 5, jw = idx & 31;
        g_xT[((size_t)b * 256 + d0 + dl) * 1024 + (j0 >> 1) + jw] =
            pk(tl[2 * jw][dl], tl[2 * jw + 1][dl]);
    }
}

__global__ void prep_w(const float* __restrict__ w1, const float* __restrict__ w2,
                       const float* __restrict__ w3) {
    __shared__ float tl[64][65];
    int blk = blockIdx.x;                        // m*32 + kt*4 + nt
    int m = blk >> 5, rem = blk & 31, kt = rem >> 2, nt = rem & 3;
    int k0 = kt * 64, n0 = nt * 64;
    const float* W = (m == 0) ? w1 : (m == 1) ? w2 : w3;
    int tid = threadIdx.x;
    #pragma unroll
    for (int p = 0; p < 4; p++) {
        int idx = tid + p * 256;
        int r = idx >> 4, c4 = idx & 15;
        float4 v = *(const float4*)(W + (size_t)(k0 + r) * DD + n0 + c4 * 4);
        tl[r][c4 * 4 + 0] = v.x; tl[r][c4 * 4 + 1] = v.y;
        tl[r][c4 * 4 + 2] = v.z; tl[r][c4 * 4 + 3] = v.w;
    }
    __syncthreads();
    #pragma unroll
    for (int p = 0; p < 4; p++) {
        int idx = tid + p * 256;
        int nl = idx >> 4, kc4 = idx & 15;
        float4 o;
        o.x = f2tf(tl[kc4 * 4 + 0][nl]); o.y = f2tf(tl[kc4 * 4 + 1][nl]);
        o.z = f2tf(tl[kc4 * 4 + 2][nl]); o.w = f2tf(tl[kc4 * 4 + 3][nl]);
        *(float4*)(g_wtf + ((size_t)m * 256 + n0 + nl) * 512 + k0 + kc4 * 4) = o;
    }
}

// ===========================================================================
// attention, warp-specialized: warps 0-3 produce S+exp->P, warps 4-7
// consume P with PV (lagging one tile). One __syncthreads per iteration.
// ===========================================================================
#define A_SU  0        // [2][64] f32 (double buffer)
#define A_INV 512      // [64] f32
#define A_LSP 768      // [2][64] f32
#define A_YS  1792     // [64][260] f32
#define A_KS  68352    // [64][260] f32 (single buffer; producer-only)
#define A_KT  134912   // [2][256][36] u32
#define A_PS  208640   // [2][64][36] u32
#define A_END 227072

__global__ __launch_bounds__(256, 1) void attn_kernel() {
    extern __shared__ char smem[];
    const uint32_t sb = smem_u32(smem);
    float* su_s  = (float*)(smem + A_SU);
    float* inv_s = (float*)(smem + A_INV);
    float* lsp   = (float*)(smem + A_LSP);
    uint32_t* Pw = (uint32_t*)(smem + A_PS);

    const int tid = threadIdx.x, w = tid >> 5, lane = tid & 31;
    const int g = lane >> 2, t = lane & 3;
    const bool producer = (w < 4);
    const int wsr = w & 1, wsc = (w >> 1) & 1;   // producer S grid 2x2 (32x32 tiles)
    const int wor = w - 4;                       // consumer d-block 0..3
    const int b = blockIdx.y, q0 = blockIdx.x * BM;
    const int bbase = b * LL;

    const int l7  = lane & 7;
    const int l8h = (lane >> 3) & 1;
    const int l16 = lane >> 4;

    // ldmatrix bases
    const uint32_t aY0 = sb + A_YS + (uint32_t)(((wsr * 32 + l7 + l8h * 8) * 260 + l16 * 4) * 4);
    const uint32_t aY1 = aY0 + 16 * 260 * 4;
    const uint32_t aKB = sb + A_KS + (uint32_t)(((wsc * 32 + l16 * 8 + l7) * 260 + l8h * 4) * 4);
    const uint32_t aT0 = sb + A_KT + (uint32_t)(((wor * 64 + l7 + l8h * 8) * 36 + l16 * 4) * 4);
    const uint32_t aP0 = sb + A_PS + (uint32_t)(((l16 * 8 + l7) * 36 + l8h * 4) * 4);

    // ---- preamble: cp.async Y, K(0), su(0) (all threads) ----
    #pragma unroll
    for (int p = 0; p < 16; p++) {
        int idx = tid + p * 256;
        int r = idx >> 6, c4 = idx & 63;
        cpa16(sb + A_YS + (r * 260 + c4 * 4) * 4,
              &g_yf[((size_t)(bbase + q0 + r)) * DD + c4 * 4]);
    }
    #pragma unroll
    for (int p = 0; p < 16; p++) {
        int idx = tid + p * 256;
        int r = idx >> 6, c4 = idx & 63;
        cpa16(sb + A_KS + (r * 260 + c4 * 4) * 4,
              &g_h[((size_t)(bbase + r)) * 512 + c4 * 4]);
    }
    if (tid < 16) cpa16(sb + A_SU + tid * 16, &g_su[bbase + tid * 4]);
    CP_COMMIT();

    float accS[2][4][4];          // producers only (live there)
    float accO[4][8][4];          // consumers only
    float lsum[2][2] = {{0.f, 0.f}, {0.f, 0.f}};
    if (!producer) {
        #pragma unroll
        for (int mi = 0; mi < 4; mi++)
            #pragma unroll
            for (int ni = 0; ni < 8; ni++)
                #pragma unroll
                for (int q = 0; q < 4; q++) accO[mi][ni][q] = 0.f;
    }

    for (int tt = 0; tt < NT; tt++) {
        CP_WAIT0();
        __syncthreads();   // publishes: K(tt), su(tt), Kt(tt-1), P(tt-1)

        // step 3: all threads issue Kt(tt) and su(tt+1)
        {
            const int jb = tt * BN;
            #pragma unroll
            for (int p = 0; p < 8; p++) {
                int idx = tid + p * 256;
                int d = idx >> 3, c = idx & 7;
                cpa16(sb + A_KT + (tt & 1) * 36864 + (d * 36 + c * 4) * 4,
                      &g_xT[((size_t)(b * 256 + d)) * 1024 + (jb >> 1) + c * 4]);
            }
            if (tt < NT - 1 && tid < 16)
                cpa16(sb + A_SU + ((tt + 1) & 1) * 256 + tid * 16,
                      &g_su[bbase + (tt + 1) * BN + tid * 4]);
            CP_COMMIT();
        }

        if (producer) {
            // ---- S(tt) = Y @ K^T : tf32, warp tile 32x32 ----
            #pragma unroll
            for (int mi = 0; mi < 2; mi++)
                #pragma unroll
                for (int ni = 0; ni < 4; ni++)
                    #pragma unroll
                    for (int q = 0; q < 4; q++) accS[mi][ni][q] = 0.f;
            #pragma unroll 8
            for (int ks = 0; ks < 32; ks++) {
                uint32_t a0[4], a1[4], bq0[4], bq1[4];
                ldsm4(a0, aY0 + ks * 32);
                ldsm4(a1, aY1 + ks * 32);
                ldsm4(bq0, aKB + ks * 32);
                ldsm4(bq1, aKB + 16 * 260 * 4 + ks * 32);
                mma_tf32(accS[0][0], a0, bq0); mma_tf32(accS[0][1], a0, bq0 + 2);
                mma_tf32(accS[0][2], a0, bq1); mma_tf32(accS[0][3], a0, bq1 + 2);
                mma_tf32(accS[1][0], a1, bq0); mma_tf32(accS[1][1], a1, bq0 + 2);
                mma_tf32(accS[1][2], a1, bq1); mma_tf32(accS[1][3], a1, bq1 + 2);
            }
            // ---- exp epilogue -> P[tt&1] ----
            const int bufP = (tt & 1) * 2304;
            #pragma unroll
            for (int mi = 0; mi < 2; mi++)
                #pragma unroll
                for (int ni = 0; ni < 4; ni++) {
                    const int c01 = wsc * 32 + ni * 8 + 2 * t;
                    const float s0 = su_s[(tt & 1) * 64 + c01];
                    const float s1 = su_s[(tt & 1) * 64 + c01 + 1];
                    float p0 = __expf(accS[mi][ni][0] + s0);
                    float p1 = __expf(accS[mi][ni][1] + s1);
                    float p2 = __expf(accS[mi][ni][2] + s0);
                    float p3 = __expf(accS[mi][ni][3] + s1);
                    lsum[mi][0] += p0 + p1;
                    lsum[mi][1] += p2 + p3;
                    const int row = wsr * 32 + mi * 16 + g;
                    const int jw = wsc * 16 + ni * 4 + t;
                    Pw[bufP + row * 36 + jw]       = pk(p0, p1);
                    Pw[bufP + (row + 8) * 36 + jw] = pk(p2, p3);
                }
            PROD_BAR();   // all producers done reading K(tt)
            if (tt < NT - 1) {   // prefetch K(tt+1) into single K buffer
                const int j1 = (tt + 1) * BN;
                #pragma unroll
                for (int p = 0; p < 32; p++) {
                    int idx = tid + p * 128;
                    int r = idx >> 6, c4 = idx & 63;
                    cpa16(sb + A_KS + (r * 260 + c4 * 4) * 4,
                          &g_h[((size_t)(bbase + j1 + r)) * 512 + c4 * 4]);
                }
                CP_COMMIT();
            }
        } else if (tt > 0) {
            // ---- consumer: O^T += Kt(tt-1) @ P(tt-1)^T ----
            const int bufC = (tt - 1) & 1;
            const uint32_t tOfs = aT0 + (uint32_t)(bufC * 36864);
            const uint32_t pOfs = aP0 + (uint32_t)(bufC * 9216);
            #pragma unroll
            for (int kj = 0; kj < 4; kj++) {
                const uint32_t jb = (uint32_t)(kj * 32);
                uint32_t a[4][4], bp0[4], bp1[4], bp2[4], bp3[4];
                #pragma unroll
                for (int mi = 0; mi < 4; mi++) ldsm4(a[mi], tOfs + mi * 2304 + jb);
                ldsm4(bp0, pOfs + jb);
                ldsm4(bp1, pOfs + 2304 + jb);
                ldsm4(bp2, pOfs + 4608 + jb);
                ldsm4(bp3, pOfs + 6912 + jb);
                #pragma unroll
                for (int mi = 0; mi < 4; mi++) {
                    mma_bf16(accO[mi][0], a[mi], bp0); mma_bf16(accO[mi][1], a[mi], bp0 + 2);
                    mma_bf16(accO[mi][2], a[mi], bp1); mma_bf16(accO[mi][3], a[mi], bp1 + 2);
                    mma_bf16(accO[mi][4], a[mi], bp2); mma_bf16(accO[mi][5], a[mi], bp2 + 2);
                    mma_bf16(accO[mi][6], a[mi], bp3); mma_bf16(accO[mi][7], a[mi], bp3 + 2);
                }
            }
        }
    }

    // ---- drain: final PV(NT-1) + lsum reduce ----
    CP_WAIT0();
    __syncthreads();
    if (producer) {
        #pragma unroll
        for (int mi = 0; mi < 2; mi++)
            #pragma unroll
            for (int rh = 0; rh < 2; rh++) {
                float v = lsum[mi][rh];
                v += __shfl_xor_sync(0xffffffffu, v, 1);
                v += __shfl_xor_sync(0xffffffffu, v, 2);
                if (t == 0) lsp[wsc * 64 + wsr * 32 + mi * 16 + rh * 8 + g] = v;
            }
    } else {
        const int bufC = (NT - 1) & 1;
        const uint32_t tOfs = aT0 + (uint32_t)(bufC * 36864);
        const uint32_t pOfs = aP0 + (uint32_t)(bufC * 9216);
        #pragma unroll
        for (int kj = 0; kj < 4; kj++) {
            const uint32_t jb = (uint32_t)(kj * 32);
            uint32_t a[4][4], bp0[4], bp1[4], bp2[4], bp3[4];
            #pragma unroll
            for (int mi = 0; mi < 4; mi++) ldsm4(a[mi], tOfs + mi * 2304 + jb);
            ldsm4(bp0, pOfs + jb);
            ldsm4(bp1, pOfs + 2304 + jb);
            ldsm4(bp2, pOfs + 4608 + jb);
            ldsm4(bp3, pOfs + 6912 + jb);
            #pragma unroll
            for (int mi = 0; mi < 4; mi++) {
                mma_bf16(accO[mi][0], a[mi], bp0); mma_bf16(accO[mi][1], a[mi], bp0 + 2);
                mma_bf16(accO[mi][2], a[mi], bp1); mma_bf16(accO[mi][3], a[mi], bp1 + 2);
                mma_bf16(accO[mi][4], a[mi], bp2); mma_bf16(accO[mi][5], a[mi], bp2 + 2);
                mma_bf16(accO[mi][6], a[mi], bp3); mma_bf16(accO[mi][7], a[mi], bp3 + 2);
            }
        }
    }
    __syncthreads();
    if (tid < 64) inv_s[tid] = 1.f / (lsp[tid] + lsp[64 + tid]);
    __syncthreads();

    // ---- consumers: normalize, tf32-round, transpose via shfl, store ----
    if (!producer) {
        const bool even = ((g & 1) == 0);
        #pragma unroll
        for (int mi = 0; mi < 4; mi++)
            #pragma unroll
            for (int ni = 0; ni < 8; ni++) {
                const int iA = ni * 8 + 2 * t;
                const float invA = inv_s[iA], invB = inv_s[iA + 1];
                float c0 = f2tf(accO[mi][ni][0] * invA), c1 = f2tf(accO[mi][ni][1] * invB);
                float c2 = f2tf(accO[mi][ni][2] * invA), c3 = f2tf(accO[mi][ni][3] * invB);
                float v0 = __shfl_xor_sync(0xffffffffu, c0, 4);
                float v1 = __shfl_xor_sync(0xffffffffu, c1, 4);
                float v2 = __shfl_xor_sync(0xffffffffu, c2, 4);
                float v3 = __shfl_xor_sync(0xffffffffu, c3, 4);
                float* rowA = g_h + ((size_t)(bbase + q0 + iA)) * 512 + 256;
                float* rowB = rowA + 512;
                if (even) {
                    const int d2 = (wor * 32 + mi * 8 + (g >> 1)) * 2;
                    *(float2*)(rowA + d2) = make_float2(c0, v0);
                    *(float2*)(rowB + d2) = make_float2(c1, v1);
                } else {
                    const int d2 = (wor * 32 + mi * 8 + ((g + 7) >> 1)) * 2;
                    *(float2*)(rowA + d2) = make_float2(v2, c2);
                    *(float2*)(rowB + d2) = make_float2(v3, c3);
                }
            }
    }
}

// ===========================================================================
// MLP tf32 (unchanged from R12): grid (128, 4), 256 thr, ldmatrix frags.
// ===========================================================================
#define M_HS 0          // [2][128][36] f32
#define M_WS 36864      // [2][192][36] f32
#define M_END 92160

__global__ __launch_bounds__(256, 1)
void mlp_kernel(const float* __restrict__ x,
                const float* __restrict__ b1, const float* __restrict__ b2,
                const float* __restrict__ b3, float* __restrict__ out)
{
    extern __shared__ char smem[];
    const uint32_t sb = smem_u32(smem);

    const int tid = threadIdx.x, w = tid >> 5, lane = tid & 31;
    const int g = lane >> 2, t = lane & 3;
    const int mw = w >> 1, nw = w & 1;
    const int row0 = blockIdx.x * 128, n0 = blockIdx.y * 64;

    const int l7  = lane & 7;
    const int l8h = (lane >> 3) & 1;
    const int l16 = lane >> 4;
    const uint32_t aH0 = sb + M_HS + (uint32_t)(((mw * 32 + l7 + l8h * 8) * 36 + l16 * 4) * 4);
    const uint32_t aW0 = sb + M_WS + (uint32_t)(((nw * 32 + l16 * 8 + l7) * 36 + l8h * 4) * 4);

    #pragma unroll
    for (int p = 0; p < 4; p++) {
        int idx = tid + p * 256;
        int r = idx >> 3, c = idx & 7;
        cpa16(sb + M_HS + (r * 36 + c * 4) * 4,
              &g_h[((size_t)(row0 + r)) * 512 + c * 4]);
    }
    #pragma unroll
    for (int p = 0; p < 6; p++) {
        int idx = tid + p * 256;
        int m = idx >> 9, rem = idx & 511;
        int n = rem >> 3, c = rem & 7;
        cpa16(sb + M_WS + ((m * 64 + n) * 36 + c * 4) * 4,
              &g_wtf[((size_t)m * 256 + n0 + n) * 512 + c * 4]);
    }
    CP_COMMIT();

    float acc[3][2][4][4];
    #pragma unroll
    for (int m = 0; m < 3; m++)
        #pragma unroll
        for (int mi = 0; mi < 2; mi++)
            #pragma unroll
            for (int ni = 0; ni < 4; ni++)
                #pragma unroll
                for (int q = 0; q < 4; q++) acc[m][mi][ni][q] = 0.f;

    for (int s = 0; s < 16; s++) {
        CP_WAIT0();
        __syncthreads();
        const int buf = s & 1;

        if (s < 15) {
            const int nb = (s + 1) & 1, k1 = (s + 1) * 32;
            #pragma unroll
            for (int p = 0; p < 4; p++) {
                int idx = tid + p * 256;
                int r = idx >> 3, c = idx & 7;
                cpa16(sb + M_HS + nb * 18432 + (r * 36 + c * 4) * 4,
                      &g_h[((size_t)(row0 + r)) * 512 + k1 + c * 4]);
            }
            #pragma unroll
            for (int p = 0; p < 6; p++) {
                int idx = tid + p * 256;
                int m = idx >> 9, rem = idx & 511;
                int n = rem >> 3, c = rem & 7;
                cpa16(sb + M_WS + nb * 27648 + ((m * 64 + n) * 36 + c * 4) * 4,
                      &g_wtf[((size_t)m * 256 + n0 + n) * 512 + k1 + c * 4]);
            }
            CP_COMMIT();
        }

        const uint32_t hOfs = aH0 + (uint32_t)(buf * 18432);
        const uint32_t wOfs = aW0 + (uint32_t)(buf * 27648);
        #pragma unroll
        for (int ks = 0; ks < 4; ks++) {
            const uint32_t kb = (uint32_t)(ks * 32);
            uint32_t a0[4], a1[4];
            ldsm4(a0, hOfs + kb);
            ldsm4(a1, hOfs + 16 * 36 * 4 + kb);
            #pragma unroll
            for (int m = 0; m < 3; m++) {
                uint32_t bq0[4], bq1[4];
                ldsm4(bq0, wOfs + m * 9216 + kb);
                ldsm4(bq1, wOfs + m * 9216 + 2304 + kb);
                mma_tf32(acc[m][0][0], a0, bq0);
                mma_tf32(acc[m][0][1], a0, bq0 + 2);
                mma_tf32(acc[m][0][2], a0, bq1);
                mma_tf32(acc[m][0][3], a0, bq1 + 2);
                mma_tf32(acc[m][1][0], a1, bq0);
                mma_tf32(acc[m][1][1], a1, bq0 + 2);
                mma_tf32(acc[m][1][2], a1, bq1);
                mma_tf32(acc[m][1][3], a1, bq1 + 2);
            }
        }
    }

    #pragma unroll
    for (int mi = 0; mi < 2; mi++)
        #pragma unroll
        for (int ni = 0; ni < 4; ni++) {
            const int rloc = mw * 32 + mi * 16 + g;
            const int cc = n0 + nw * 32 + ni * 8 + 2 * t;
            const float2 bb1 = *(const float2*)(b1 + cc);
            const float2 bb2 = *(const float2*)(b2 + cc);
            const float2 bb3 = *(const float2*)(b3 + cc);
            #pragma unroll
            for (int h = 0; h < 2; h++) {
                const int rl = rloc + h * 8, i0 = h * 2;
                float z0 = tanhf(acc[0][mi][ni][i0]     + bb1.x);
                float z1 = tanhf(acc[0][mi][ni][i0 + 1] + bb1.y);
                float r0 = 1.f / (1.f + __expf(-(acc[1][mi][ni][i0]     + bb2.x)));
                float r1 = 1.f / (1.f + __expf(-(acc[1][mi][ni][i0 + 1] + bb2.y)));
                float f0 = 1.f / (1.f + __expf(-(acc[2][mi][ni][i0]     + bb3.x)));
                float f1 = 1.f / (1.f + __expf(-(acc[2][mi][ni][i0 + 1] + bb3.y)));
                const float2 xv = *(const float2*)(x + (size_t)(row0 + rl) * DD + cc);
                float2 o = make_float2(r0 * xv.x + f0 * z0, r1 * xv.y + f1 * z1);
                *(float2*)(out + (size_t)(row0 + rl) * DD + cc) = o;
            }
        }
}

// ===========================================================================
extern "C" void kernel_launch(void* const* d_in, const int* in_sizes, int n_in,
                              void* d_out, int out_size)
{
    const float* x   = (const float*)d_in[0];
    const float* wia = (const float*)d_in[1];
    const float* w1  = (const float*)d_in[2];
    const float* w2  = (const float*)d_in[3];
    const float* w3  = (const float*)d_in[4];
    const float* b1  = (const float*)d_in[5];
    const float* b2  = (const float*)d_in[6];
    const float* b3  = (const float*)d_in[7];
    float* out = (float*)d_out;

    cudaFuncSetAttribute(attn_kernel, cudaFuncAttributeMaxDynamicSharedMemorySize, A_END);
    cudaFuncSetAttribute(mlp_kernel,  cudaFuncAttributeMaxDynamicSharedMemorySize, M_END);

    prep_su  <<<LL * BB / 8, 256>>>(x, wia);
    prep_pack<<<BB * 128, 256>>>(x, wia);
    prep_w   <<<96, 256>>>(w1, w2, w3);
    attn_kernel<<<dim3(LL / BM, BB), 256, A_END>>>();
    mlp_kernel <<<dim3(BB * LL / 128, 4), 256, M_END>>>(x, b1, b2, b3, out);
}

// round 14
// speedup vs baseline: 1.1140x; 1.1140x over previous
#include <cuda_runtime.h>
#include <cstdint>

#define BB 8
#define LL 2048
#define DD 256
#define BM 64
#define BN 64
#define NT (LL / BN)

// ---- global scratch (allocation-free device arrays) ----
__device__ float    g_yf[(size_t)BB * LL * DD];     // tf32(x*wp)
__device__ float    g_h [(size_t)BB * LL * 512];    // [tf32(x) | tf32(attn)]
__device__ uint32_t g_xT[(size_t)BB * 256 * 1024];  // x^T bf16 j-pairs
__device__ float    g_su[(size_t)BB * LL];
__device__ float    g_wtf[3 * 256 * 512];           // W^T tf32 [m][n][k]

// ---- helpers ----
__device__ __forceinline__ uint32_t smem_u32(const void* p) {
    uint32_t a;
    asm("{ .reg .u64 t; cvta.to.shared.u64 t, %1; cvt.u32.u64 %0, t; }" : "=r"(a) : "l"(p));
    return a;
}
__device__ __forceinline__ uint32_t pk(float lo, float hi) {
    uint32_t r; asm("cvt.rn.bf16x2.f32 %0, %1, %2;" : "=r"(r) : "f"(hi), "f"(lo)); return r;
}
__device__ __forceinline__ float bf_lo(uint32_t u) { return __uint_as_float(u << 16); }
__device__ __forceinline__ float bf_hi(uint32_t u) { return __uint_as_float(u & 0xffff0000u); }
__device__ __forceinline__ float f2tf(float f) {
    uint32_t u; asm("cvt.rna.tf32.f32 %0, %1;" : "=r"(u) : "f"(f)); return __uint_as_float(u);
}
__device__ __forceinline__ void cpa16(uint32_t dst, const void* src) {
    asm volatile("cp.async.ca.shared.global [%0], [%1], 16;" :: "r"(dst), "l"(src));
}
#define CP_COMMIT() asm volatile("cp.async.commit_group;")
#define CP_WAIT0()  asm volatile("cp.async.wait_group 0;")

__device__ __forceinline__ void ldsm4(uint32_t* r, uint32_t addr) {
    asm volatile("ldmatrix.sync.aligned.m8n8.x4.shared.b16 {%0,%1,%2,%3}, [%4];"
        : "=r"(r[0]), "=r"(r[1]), "=r"(r[2]), "=r"(r[3]) : "r"(addr));
}
__device__ __forceinline__ void mma_bf16(float* c, const uint32_t* a, const uint32_t* b) {
    asm volatile("mma.sync.aligned.m16n8k16.row.col.f32.bf16.bf16.f32 "
        "{%0,%1,%2,%3}, {%4,%5,%6,%7}, {%8,%9}, {%0,%1,%2,%3};"
        : "+f"(c[0]), "+f"(c[1]), "+f"(c[2]), "+f"(c[3])
        : "r"(a[0]), "r"(a[1]), "r"(a[2]), "r"(a[3]), "r"(b[0]), "r"(b[1]));
}
__device__ __forceinline__ void mma_tf32(float* c, const uint32_t* a, const uint32_t* b) {
    asm volatile("mma.sync.aligned.m16n8k8.row.col.f32.tf32.tf32.f32 "
        "{%0,%1,%2,%3}, {%4,%5,%6,%7}, {%8,%9}, {%0,%1,%2,%3};"
        : "+f"(c[0]), "+f"(c[1]), "+f"(c[2]), "+f"(c[3])
        : "r"(a[0]), "r"(a[1]), "r"(a[2]), "r"(a[3]), "r"(b[0]), "r"(b[1]));
}

// ===========================================================================
// prep kernels (unchanged)
// ===========================================================================
__global__ void prep_su(const float* __restrict__ x, const float* __restrict__ w_itr) {
    int row = blockIdx.x * 8 + (threadIdx.x >> 5);
    int lane = threadIdx.x & 31;
    const float* xr = x + (size_t)row * DD;
    float s = 0.f;
    #pragma unroll
    for (int k = 0; k < 8; k++) s += xr[lane + 32 * k] * w_itr[lane + 32 * k];
    #pragma unroll
    for (int off = 16; off > 0; off >>= 1) s += __shfl_xor_sync(0xffffffffu, s, off);
    if (lane == 0) g_su[row] = s;
}

__global__ void prep_pack(const float* __restrict__ x, const float* __restrict__ w_itr) {
    __shared__ float tl[64][65];
    int blk = blockIdx.x;
    int b = blk >> 7, rem = blk & 127, jt = rem >> 2, dt = rem & 3;
    int j0 = jt * 64, d0 = dt * 64;
    const float* xb = x + ((size_t)b * LL + j0) * DD + d0;
    int tid = threadIdx.x;
    #pragma unroll
    for (int p = 0; p < 4; p++) {
        int idx = tid + p * 256;
        int r = idx >> 4, c4 = idx & 15;
        float4 v = *(const float4*)(xb + (size_t)r * DD + c4 * 4);
        tl[r][c4 * 4 + 0] = v.x; tl[r][c4 * 4 + 1] = v.y;
        tl[r][c4 * 4 + 2] = v.z; tl[r][c4 * 4 + 3] = v.w;
    }
    __syncthreads();
    const float* wp = w_itr + 2 * DD;
    #pragma unroll
    for (int p = 0; p < 4; p++) {
        int idx = tid + p * 256;
        int r = idx >> 4, c4 = idx & 15;
        float a0 = tl[r][c4 * 4 + 0], a1 = tl[r][c4 * 4 + 1];
        float a2 = tl[r][c4 * 4 + 2], a3 = tl[r][c4 * 4 + 3];
        float4 y, h;
        y.x = f2tf(a0 * wp[d0 + c4 * 4 + 0]); y.y = f2tf(a1 * wp[d0 + c4 * 4 + 1]);
        y.z = f2tf(a2 * wp[d0 + c4 * 4 + 2]); y.w = f2tf(a3 * wp[d0 + c4 * 4 + 3]);
        h.x = f2tf(a0); h.y = f2tf(a1); h.z = f2tf(a2); h.w = f2tf(a3);
        *(float4*)(g_yf + ((size_t)b * LL + j0 + r) * DD + d0 + c4 * 4) = y;
        *(float4*)(g_h  + ((size_t)b * LL + j0 + r) * 512 + d0 + c4 * 4) = h;
    }
    #pragma unroll
    for (int p = 0; p < 8; p++) {
        int idx = tid + p * 256;
        int dl = idx >> 5, jw = idx & 31;
        g_xT[((size_t)b * 256 + d0 + dl) * 1024 + (j0 >> 1) + jw] =
            pk(tl[2 * jw][dl], tl[2 * jw + 1][dl]);
    }
}

__global__ void prep_w(const float* __restrict__ w1, const float* __restrict__ w2,
                       const float* __restrict__ w3) {
    __shared__ float tl[64][65];
    int blk = blockIdx.x;
    int m = blk >> 5, rem = blk & 31, kt = rem >> 2, nt = rem & 3;
    int k0 = kt * 64, n0 = nt * 64;
    const float* W = (m == 0) ? w1 : (m == 1) ? w2 : w3;
    int tid = threadIdx.x;
    #pragma unroll
    for (int p = 0; p < 4; p++) {
        int idx = tid + p * 256;
        int r = idx >> 4, c4 = idx & 15;
        float4 v = *(const float4*)(W + (size_t)(k0 + r) * DD + n0 + c4 * 4);
        tl[r][c4 * 4 + 0] = v.x; tl[r][c4 * 4 + 1] = v.y;
        tl[r][c4 * 4 + 2] = v.z; tl[r][c4 * 4 + 3] = v.w;
    }
    __syncthreads();
    #pragma unroll
    for (int p = 0; p < 4; p++) {
        int idx = tid + p * 256;
        int nl = idx >> 4, kc4 = idx & 15;
        float4 o;
        o.x = f2tf(tl[kc4 * 4 + 0][nl]); o.y = f2tf(tl[kc4 * 4 + 1][nl]);
        o.z = f2tf(tl[kc4 * 4 + 2][nl]); o.w = f2tf(tl[kc4 * 4 + 3][nl]);
        *(float4*)(g_wtf + ((size_t)m * 256 + n0 + nl) * 512 + k0 + kc4 * 4) = o;
    }
}

// ===========================================================================
// attention: S split over d-halves with exp-product combine.
// Warp roles (S): i2=w&1, j2=(w>>1)&1, kh=w>>2 — 32x32 tile over 128 d.
// kh0: Pa = bf16(exp(S1)); kh1: P = Pa * exp(S2+su), lsum. PV: R12 layout.
// ===========================================================================
#define A_SU  0        // [2][64] f32
#define A_INV 512      // [64] f32
#define A_LSP 768      // [2][64] f32
#define A_YS  1792     // [64][260] f32
#define A_KS  68352    // [64][260] f32 (single buffer)
#define A_KT  134912   // [2][256][36] u32
#define A_PS  208640   // [64][36] u32 (P product)
#define A_PA  217856   // [64][36] u32 (exp(S1) partial)
#define A_END 227072

__global__ __launch_bounds__(256, 1) void attn_kernel() {
    extern __shared__ char smem[];
    const uint32_t sb = smem_u32(smem);
    float* su_s  = (float*)(smem + A_SU);
    float* inv_s = (float*)(smem + A_INV);
    float* lsp   = (float*)(smem + A_LSP);
    uint32_t* Pw  = (uint32_t*)(smem + A_PS);
    uint32_t* Paw = (uint32_t*)(smem + A_PA);

    const int tid = threadIdx.x, w = tid >> 5, lane = tid & 31;
    const int g = lane >> 2, t = lane & 3;
    const int i2 = w & 1, j2 = (w >> 1) & 1, kh = w >> 2;   // S roles
    const int wor = w & 3, woc = w >> 2;                    // PV grid 4x2
    const int b = blockIdx.y, q0 = blockIdx.x * BM;
    const int bbase = b * LL;

    const int l7  = lane & 7;
    const int l8h = (lane >> 3) & 1;
    const int l16 = lane >> 4;

    // S-phase ldmatrix bases (d offset kh*128 words)
    const uint32_t aY0 = sb + A_YS +
        (uint32_t)(((i2 * 32 + l7 + l8h * 8) * 260 + l16 * 4 + kh * 128) * 4);
    const uint32_t aY1 = aY0 + 16 * 260 * 4;
    const uint32_t aKB0 = sb + A_KS +
        (uint32_t)(((j2 * 32 + l16 * 8 + l7) * 260 + l8h * 4 + kh * 128) * 4);
    const uint32_t aKB1 = aKB0 + 16 * 260 * 4;
    // PV bases (R12)
    const uint32_t aT0 = sb + A_KT + (uint32_t)(((wor * 64 + l7 + l8h * 8) * 36 + l16 * 4) * 4);
    const uint32_t aP0 = sb + A_PS + (uint32_t)(((woc * 32 + l16 * 8 + l7) * 36 + l8h * 4) * 4);

    // ---- preamble: cp.async Y, K(0), Kt(0), su(0) ----
    #pragma unroll
    for (int p = 0; p < 16; p++) {
        int idx = tid + p * 256;
        int r = idx >> 6, c4 = idx & 63;
        cpa16(sb + A_YS + (r * 260 + c4 * 4) * 4,
              &g_yf[((size_t)(bbase + q0 + r)) * DD + c4 * 4]);
    }
    #pragma unroll
    for (int p = 0; p < 16; p++) {
        int idx = tid + p * 256;
        int r = idx >> 6, c4 = idx & 63;
        cpa16(sb + A_KS + (r * 260 + c4 * 4) * 4,
              &g_h[((size_t)(bbase + r)) * 512 + c4 * 4]);
    }
    #pragma unroll
    for (int p = 0; p < 8; p++) {
        int idx = tid + p * 256;
        int d = idx >> 3, c = idx & 7;
        cpa16(sb + A_KT + (d * 36 + c * 4) * 4,
              &g_xT[((size_t)(b * 256 + d)) * 1024 + c * 4]);
    }
    if (tid < 16) cpa16(sb + A_SU + tid * 16, &g_su[bbase + tid * 4]);
    CP_COMMIT();

    float accO[4][4][4];
    #pragma unroll
    for (int mi = 0; mi < 4; mi++)
        #pragma unroll
        for (int ni = 0; ni < 4; ni++)
            #pragma unroll
            for (int q = 0; q < 4; q++) accO[mi][ni][q] = 0.f;
    float lsum[2][2] = {{0.f, 0.f}, {0.f, 0.f}};

    for (int tt = 0; tt < NT; tt++) {
        CP_WAIT0();
        __syncthreads();
        const int buf = tt & 1;

        if (tt < NT - 1) {               // prefetch Kt(t+1)/su(t+1)
            const int nb = (tt + 1) & 1, j1 = (tt + 1) * BN;
            #pragma unroll
            for (int p = 0; p < 8; p++) {
                int idx = tid + p * 256;
                int d = idx >> 3, c = idx & 7;
                cpa16(sb + A_KT + nb * 36864 + (d * 36 + c * 4) * 4,
                      &g_xT[((size_t)(b * 256 + d)) * 1024 + (j1 >> 1) + c * 4]);
            }
            if (tid < 16) cpa16(sb + A_SU + nb * 256 + tid * 16, &g_su[bbase + j1 + tid * 4]);
            CP_COMMIT();
        }

        // ---- S partial = Y @ K^T over this warp's d-half: 32x32, 16 ks ----
        float accS[2][4][4];
        #pragma unroll
        for (int mi = 0; mi < 2; mi++)
            #pragma unroll
            for (int ni = 0; ni < 4; ni++)
                #pragma unroll
                for (int q = 0; q < 4; q++) accS[mi][ni][q] = 0.f;
        #pragma unroll 8
        for (int ks = 0; ks < 16; ks++) {
            uint32_t a0[4], a1[4], bq0[4], bq1[4];
            ldsm4(a0, aY0 + ks * 32);
            ldsm4(a1, aY1 + ks * 32);
            ldsm4(bq0, aKB0 + ks * 32);
            ldsm4(bq1, aKB1 + ks * 32);
            mma_tf32(accS[0][0], a0, bq0); mma_tf32(accS[0][1], a0, bq0 + 2);
            mma_tf32(accS[0][2], a0, bq1); mma_tf32(accS[0][3], a0, bq1 + 2);
            mma_tf32(accS[1][0], a1, bq0); mma_tf32(accS[1][1], a1, bq0 + 2);
            mma_tf32(accS[1][2], a1, bq1); mma_tf32(accS[1][3], a1, bq1 + 2);
        }

        // ---- kh0: Pa = bf16(exp(S1)) ----
        if (kh == 0) {
            #pragma unroll
            for (int mi = 0; mi < 2; mi++)
                #pragma unroll
                for (int ni = 0; ni < 4; ni++) {
                    const int row = i2 * 32 + mi * 16 + g;
                    const int jw = j2 * 16 + ni * 4 + t;
                    float p0 = __expf(accS[mi][ni][0]);
                    float p1 = __expf(accS[mi][ni][1]);
                    float p2 = __expf(accS[mi][ni][2]);
                    float p3 = __expf(accS[mi][ni][3]);
                    Paw[row * 36 + jw]       = pk(p0, p1);
                    Paw[(row + 8) * 36 + jw] = pk(p2, p3);
                }
        }
        __syncthreads();                 // Pa visible; all K(tt) reads done

        if (kh == 1) {
            // ---- kh1: P = Pa * exp(S2 + su), lsum ----
            #pragma unroll
            for (int mi = 0; mi < 2; mi++)
                #pragma unroll
                for (int ni = 0; ni < 4; ni++) {
                    const int c01 = j2 * 32 + ni * 8 + 2 * t;
                    const float s0 = su_s[buf * 64 + c01], s1 = su_s[buf * 64 + c01 + 1];
                    const int row = i2 * 32 + mi * 16 + g;
                    const int jw = j2 * 16 + ni * 4 + t;
                    const uint32_t ua = Paw[row * 36 + jw];
                    const uint32_t ub = Paw[(row + 8) * 36 + jw];
                    float q0 = __expf(accS[mi][ni][0] + s0) * bf_lo(ua);
                    float q1 = __expf(accS[mi][ni][1] + s1) * bf_hi(ua);
                    float q2 = __expf(accS[mi][ni][2] + s0) * bf_lo(ub);
                    float q3 = __expf(accS[mi][ni][3] + s1) * bf_hi(ub);
                    lsum[mi][0] += q0 + q1;
                    lsum[mi][1] += q2 + q3;
                    Pw[row * 36 + jw]       = pk(q0, q1);
                    Pw[(row + 8) * 36 + jw] = pk(q2, q3);
                }
        } else if (tt < NT - 1) {
            // ---- kh0 warps: issue K(t+1) while kh1 multiplies ----
            const int j1 = (tt + 1) * BN;
            #pragma unroll
            for (int p = 0; p < 32; p++) {
                int idx = tid + p * 128;      // tid < 128 here
                int r = idx >> 6, c4 = idx & 63;
                cpa16(sb + A_KS + (r * 260 + c4 * 4) * 4,
                      &g_h[((size_t)(bbase + j1 + r)) * 512 + c4 * 4]);
            }
            CP_COMMIT();
        }
        __syncthreads();                 // P product visible

        // ---- O^T += Kt @ P^T : bf16, warp tile 64d x 32i (R12) ----
        const uint32_t tOfs = aT0 + (uint32_t)(buf * 36864);
        #pragma unroll
        for (int kj = 0; kj < 4; kj++) {
            const uint32_t jb = (uint32_t)(kj * 32);
            uint32_t a[4][4], bp0[4], bp1[4];
            #pragma unroll
            for (int mi = 0; mi < 4; mi++) ldsm4(a[mi], tOfs + mi * 2304 + jb);
            ldsm4(bp0, aP0 + jb);
            ldsm4(bp1, aP0 + 2304 + jb);
            #pragma unroll
            for (int mi = 0; mi < 4; mi++) {
                mma_bf16(accO[mi][0], a[mi], bp0);
                mma_bf16(accO[mi][1], a[mi], bp0 + 2);
                mma_bf16(accO[mi][2], a[mi], bp1);
                mma_bf16(accO[mi][3], a[mi], bp1 + 2);
            }
        }
    }

    // ---- lsum reduce (kh1 warps only hold sums) ----
    if (kh == 1) {
        #pragma unroll
        for (int mi = 0; mi < 2; mi++)
            #pragma unroll
            for (int rh = 0; rh < 2; rh++) {
                float v = lsum[mi][rh];
                v += __shfl_xor_sync(0xffffffffu, v, 1);
                v += __shfl_xor_sync(0xffffffffu, v, 2);
                if (t == 0) lsp[j2 * 64 + i2 * 32 + mi * 16 + rh * 8 + g] = v;
            }
    }
    __syncthreads();
    if (tid < 64) inv_s[tid] = 1.f / (lsp[tid] + lsp[64 + tid]);
    __syncthreads();

    // ---- normalize, tf32-round, transpose via shfl, store to g_h ----
    const bool even = ((g & 1) == 0);
    #pragma unroll
    for (int mi = 0; mi < 4; mi++)
        #pragma unroll
        for (int ni = 0; ni < 4; ni++) {
            const int iA = woc * 32 + ni * 8 + 2 * t;
            const float invA = inv_s[iA], invB = inv_s[iA + 1];
            float c0 = f2tf(accO[mi][ni][0] * invA), c1 = f2tf(accO[mi][ni][1] * invB);
            float c2 = f2tf(accO[mi][ni][2] * invA), c3 = f2tf(accO[mi][ni][3] * invB);
            float v0 = __shfl_xor_sync(0xffffffffu, c0, 4);
            float v1 = __shfl_xor_sync(0xffffffffu, c1, 4);
            float v2 = __shfl_xor_sync(0xffffffffu, c2, 4);
            float v3 = __shfl_xor_sync(0xffffffffu, c3, 4);
            float* rowA = g_h + ((size_t)(bbase + q0 + iA)) * 512 + 256;
            float* rowB = rowA + 512;
            if (even) {
                const int d2 = (wor * 32 + mi * 8 + (g >> 1)) * 2;
                *(float2*)(rowA + d2) = make_float2(c0, v0);
                *(float2*)(rowB + d2) = make_float2(c1, v1);
            } else {
                const int d2 = (wor * 32 + mi * 8 + ((g + 7) >> 1)) * 2;
                *(float2*)(rowA + d2) = make_float2(v2, c2);
                *(float2*)(rowB + d2) = make_float2(v3, c3);
            }
        }
}

// ===========================================================================
// MLP tf32 (unchanged from R12): grid (128, 4), 256 thr, ldmatrix frags.
// ===========================================================================
#define M_HS 0
#define M_WS 36864
#define M_END 92160

__global__ __launch_bounds__(256, 1)
void mlp_kernel(const float* __restrict__ x,
                const float* __restrict__ b1, const float* __restrict__ b2,
                const float* __restrict__ b3, float* __restrict__ out)
{
    extern __shared__ char smem[];
    const uint32_t sb = smem_u32(smem);

    const int tid = threadIdx.x, w = tid >> 5, lane = tid & 31;
    const int g = lane >> 2, t = lane & 3;
    const int mw = w >> 1, nw = w & 1;
    const int row0 = blockIdx.x * 128, n0 = blockIdx.y * 64;

    const int l7  = lane & 7;
    const int l8h = (lane >> 3) & 1;
    const int l16 = lane >> 4;
    const uint32_t aH0 = sb + M_HS + (uint32_t)(((mw * 32 + l7 + l8h * 8) * 36 + l16 * 4) * 4);
    const uint32_t aW0 = sb + M_WS + (uint32_t)(((nw * 32 + l16 * 8 + l7) * 36 + l8h * 4) * 4);

    #pragma unroll
    for (int p = 0; p < 4; p++) {
        int idx = tid + p * 256;
        int r = idx >> 3, c = idx & 7;
        cpa16(sb + M_HS + (r * 36 + c * 4) * 4,
              &g_h[((size_t)(row0 + r)) * 512 + c * 4]);
    }
    #pragma unroll
    for (int p = 0; p < 6; p++) {
        int idx = tid + p * 256;
        int m = idx >> 9, rem = idx & 511;
        int n = rem >> 3, c = rem & 7;
        cpa16(sb + M_WS + ((m * 64 + n) * 36 + c * 4) * 4,
              &g_wtf[((size_t)m * 256 + n0 + n) * 512 + c * 4]);
    }
    CP_COMMIT();

    float acc[3][2][4][4];
    #pragma unroll
    for (int m = 0; m < 3; m++)
        #pragma unroll
        for (int mi = 0; mi < 2; mi++)
            #pragma unroll
            for (int ni = 0; ni < 4; ni++)
                #pragma unroll
                for (int q = 0; q < 4; q++) acc[m][mi][ni][q] = 0.f;

    for (int s = 0; s < 16; s++) {
        CP_WAIT0();
        __syncthreads();
        const int buf = s & 1;

        if (s < 15) {
            const int nb = (s + 1) & 1, k1 = (s + 1) * 32;
            #pragma unroll
            for (int p = 0; p < 4; p++) {
                int idx = tid + p * 256;
                int r = idx >> 3, c = idx & 7;
                cpa16(sb + M_HS + nb * 18432 + (r * 36 + c * 4) * 4,
                      &g_h[((size_t)(row0 + r)) * 512 + k1 + c * 4]);
            }
            #pragma unroll
            for (int p = 0; p < 6; p++) {
                int idx = tid + p * 256;
                int m = idx >> 9, rem = idx & 511;
                int n = rem >> 3, c = rem & 7;
                cpa16(sb + M_WS + nb * 27648 + ((m * 64 + n) * 36 + c * 4) * 4,
                      &g_wtf[((size_t)m * 256 + n0 + n) * 512 + k1 + c * 4]);
            }
            CP_COMMIT();
        }

        const uint32_t hOfs = aH0 + (uint32_t)(buf * 18432);
        const uint32_t wOfs = aW0 + (uint32_t)(buf * 27648);
        #pragma unroll
        for (int ks = 0; ks < 4; ks++) {
            const uint32_t kb = (uint32_t)(ks * 32);
            uint32_t a0[4], a1[4];
            ldsm4(a0, hOfs + kb);
            ldsm4(a1, hOfs + 16 * 36 * 4 + kb);
            #pragma unroll
            for (int m = 0; m < 3; m++) {
                uint32_t bq0[4], bq1[4];
                ldsm4(bq0, wOfs + m * 9216 + kb);
                ldsm4(bq1, wOfs + m * 9216 + 2304 + kb);
                mma_tf32(acc[m][0][0], a0, bq0);
                mma_tf32(acc[m][0][1], a0, bq0 + 2);
                mma_tf32(acc[m][0][2], a0, bq1);
                mma_tf32(acc[m][0][3], a0, bq1 + 2);
                mma_tf32(acc[m][1][0], a1, bq0);
                mma_tf32(acc[m][1][1], a1, bq0 + 2);
                mma_tf32(acc[m][1][2], a1, bq1);
                mma_tf32(acc[m][1][3], a1, bq1 + 2);
            }
        }
    }

    #pragma unroll
    for (int mi = 0; mi < 2; mi++)
        #pragma unroll
        for (int ni = 0; ni < 4; ni++) {
            const int rloc = mw * 32 + mi * 16 + g;
            const int cc = n0 + nw * 32 + ni * 8 + 2 * t;
            const float2 bb1 = *(const float2*)(b1 + cc);
            const float2 bb2 = *(const float2*)(b2 + cc);
            const float2 bb3 = *(const float2*)(b3 + cc);
            #pragma unroll
            for (int h = 0; h < 2; h++) {
                const int rl = rloc + h * 8, i0 = h * 2;
                float z0 = tanhf(acc[0][mi][ni][i0]     + bb1.x);
                float z1 = tanhf(acc[0][mi][ni][i0 + 1] + bb1.y);
                float r0 = 1.f / (1.f + __expf(-(acc[1][mi][ni][i0]     + bb2.x)));
                float r1 = 1.f / (1.f + __expf(-(acc[1][mi][ni][i0 + 1] + bb2.y)));
                float f0 = 1.f / (1.f + __expf(-(acc[2][mi][ni][i0]     + bb3.x)));
                float f1 = 1.f / (1.f + __expf(-(acc[2][mi][ni][i0 + 1] + bb3.y)));
                const float2 xv = *(const float2*)(x + (size_t)(row0 + rl) * DD + cc);
                float2 o = make_float2(r0 * xv.x + f0 * z0, r1 * xv.y + f1 * z1);
                *(float2*)(out + (size_t)(row0 + rl) * DD + cc) = o;
            }
        }
}

// ===========================================================================
extern "C" void kernel_launch(void* const* d_in, const int* in_sizes, int n_in,
                              void* d_out, int out_size)
{
    const float* x   = (const float*)d_in[0];
    const float* wia = (const float*)d_in[1];
    const float* w1  = (const float*)d_in[2];
    const float* w2  = (const float*)d_in[3];
    const float* w3  = (const float*)d_in[4];
    const float* b1  = (const float*)d_in[5];
    const float* b2  = (const float*)d_in[6];
    const float* b3  = (const float*)d_in[7];
    float* out = (float*)d_out;

    cudaFuncSetAttribute(attn_kernel, cudaFuncAttributeMaxDynamicSharedMemorySize, A_END);
    cudaFuncSetAttribute(mlp_kernel,  cudaFuncAttributeMaxDynamicSharedMemorySize, M_END);

    prep_su  <<<LL * BB / 8, 256>>>(x, wia);
    prep_pack<<<BB * 128, 256>>>(x, wia);
    prep_w   <<<96, 256>>>(w1, w2, w3);
    attn_kernel<<<dim3(LL / BM, BB), 256, A_END>>>();
    mlp_kernel <<<dim3(BB * LL / 128, 4), 256, M_END>>>(x, b1, b2, b3, out);
}

// round 15
// speedup vs baseline: 1.1326x; 1.0167x over previous
#include <cuda_runtime.h>
#include <cstdint>

#define BB 8
#define LL 2048
#define DD 256
#define BM 64
#define BN 64
#define NT (LL / BN)

// ---- global scratch (allocation-free device arrays) ----
__device__ float    g_yf[(size_t)BB * LL * DD];     // tf32(x*wp)
__device__ float    g_h [(size_t)BB * LL * 512];    // [tf32(x) | tf32(attn)]
__device__ uint32_t g_xT[(size_t)BB * 256 * 1024];  // x^T bf16 j-pairs
__device__ float    g_su[(size_t)BB * LL];
__device__ float    g_wtf[3 * 256 * 512];           // W^T tf32 [m][n][k]

// ---- helpers ----
__device__ __forceinline__ uint32_t smem_u32(const void* p) {
    uint32_t a;
    asm("{ .reg .u64 t; cvta.to.shared.u64 t, %1; cvt.u32.u64 %0, t; }" : "=r"(a) : "l"(p));
    return a;
}
__device__ __forceinline__ uint32_t pk(float lo, float hi) {
    uint32_t r; asm("cvt.rn.bf16x2.f32 %0, %1, %2;" : "=r"(r) : "f"(hi), "f"(lo)); return r;
}
__device__ __forceinline__ float f2tf(float f) {
    uint32_t u; asm("cvt.rna.tf32.f32 %0, %1;" : "=r"(u) : "f"(f)); return __uint_as_float(u);
}
__device__ __forceinline__ void cpa16(uint32_t dst, const void* src) {
    asm volatile("cp.async.ca.shared.global [%0], [%1], 16;" :: "r"(dst), "l"(src));
}
#define CP_COMMIT() asm volatile("cp.async.commit_group;")
#define CP_WAIT0()  asm volatile("cp.async.wait_group 0;")

__device__ __forceinline__ void ldsm4(uint32_t* r, uint32_t addr) {
    asm volatile("ldmatrix.sync.aligned.m8n8.x4.shared.b16 {%0,%1,%2,%3}, [%4];"
        : "=r"(r[0]), "=r"(r[1]), "=r"(r[2]), "=r"(r[3]) : "r"(addr));
}
__device__ __forceinline__ void mma_bf16(float* c, const uint32_t* a, const uint32_t* b) {
    asm volatile("mma.sync.aligned.m16n8k16.row.col.f32.bf16.bf16.f32 "
        "{%0,%1,%2,%3}, {%4,%5,%6,%7}, {%8,%9}, {%0,%1,%2,%3};"
        : "+f"(c[0]), "+f"(c[1]), "+f"(c[2]), "+f"(c[3])
        : "r"(a[0]), "r"(a[1]), "r"(a[2]), "r"(a[3]), "r"(b[0]), "r"(b[1]));
}
__device__ __forceinline__ void mma_tf32(float* c, const uint32_t* a, const uint32_t* b) {
    asm volatile("mma.sync.aligned.m16n8k8.row.col.f32.tf32.tf32.f32 "
        "{%0,%1,%2,%3}, {%4,%5,%6,%7}, {%8,%9}, {%0,%1,%2,%3};"
        : "+f"(c[0]), "+f"(c[1]), "+f"(c[2]), "+f"(c[3])
        : "r"(a[0]), "r"(a[1]), "r"(a[2]), "r"(a[3]), "r"(b[0]), "r"(b[1]));
}

// ===========================================================================
// prep kernels (unchanged)
// ===========================================================================
__global__ void prep_su(const float* __restrict__ x, const float* __restrict__ w_itr) {
    int row = blockIdx.x * 8 + (threadIdx.x >> 5);
    int lane = threadIdx.x & 31;
    const float* xr = x + (size_t)row * DD;
    float s = 0.f;
    #pragma unroll
    for (int k = 0; k < 8; k++) s += xr[lane + 32 * k] * w_itr[lane + 32 * k];
    #pragma unroll
    for (int off = 16; off > 0; off >>= 1) s += __shfl_xor_sync(0xffffffffu, s, off);
    if (lane == 0) g_su[row] = s;
}

__global__ void prep_pack(const float* __restrict__ x, const float* __restrict__ w_itr) {
    __shared__ float tl[64][65];
    int blk = blockIdx.x;
    int b = blk >> 7, rem = blk & 127, jt = rem >> 2, dt = rem & 3;
    int j0 = jt * 64, d0 = dt * 64;
    const float* xb = x + ((size_t)b * LL + j0) * DD + d0;
    int tid = threadIdx.x;
    #pragma unroll
    for (int p = 0; p < 4; p++) {
        int idx = tid + p * 256;
        int r = idx >> 4, c4 = idx & 15;
        float4 v = *(const float4*)(xb + (size_t)r * DD + c4 * 4);
        tl[r][c4 * 4 + 0] = v.x; tl[r][c4 * 4 + 1] = v.y;
        tl[r][c4 * 4 + 2] = v.z; tl[r][c4 * 4 + 3] = v.w;
    }
    __syncthreads();
    const float* wp = w_itr + 2 * DD;
    #pragma unroll
    for (int p = 0; p < 4; p++) {
        int idx = tid + p * 256;
        int r = idx >> 4, c4 = idx & 15;
        float a0 = tl[r][c4 * 4 + 0], a1 = tl[r][c4 * 4 + 1];
        float a2 = tl[r][c4 * 4 + 2], a3 = tl[r][c4 * 4 + 3];
        float4 y, h;
        y.x = f2tf(a0 * wp[d0 + c4 * 4 + 0]); y.y = f2tf(a1 * wp[d0 + c4 * 4 + 1]);
        y.z = f2tf(a2 * wp[d0 + c4 * 4 + 2]); y.w = f2tf(a3 * wp[d0 + c4 * 4 + 3]);
        h.x = f2tf(a0); h.y = f2tf(a1); h.z = f2tf(a2); h.w = f2tf(a3);
        *(float4*)(g_yf + ((size_t)b * LL + j0 + r) * DD + d0 + c4 * 4) = y;
        *(float4*)(g_h  + ((size_t)b * LL + j0 + r) * 512 + d0 + c4 * 4) = h;
    }
    #pragma unroll
    for (int p = 0; p < 8; p++) {
        int idx = tid + p * 256;
        int dl = idx >> 5, jw = idx & 31;
        g_xT[((size_t)b * 256 + d0 + dl) * 1024 + (j0 >> 1) + jw] =
            pk(tl[2 * jw][dl], tl[2 * jw + 1][dl]);
    }
}

__global__ void prep_w(const float* __restrict__ w1, const float* __restrict__ w2,
                       const float* __restrict__ w3) {
    __shared__ float tl[64][65];
    int blk = blockIdx.x;
    int m = blk >> 5, rem = blk & 31, kt = rem >> 2, nt = rem & 3;
    int k0 = kt * 64, n0 = nt * 64;
    const float* W = (m == 0) ? w1 : (m == 1) ? w2 : w3;
    int tid = threadIdx.x;
    #pragma unroll
    for (int p = 0; p < 4; p++) {
        int idx = tid + p * 256;
        int r = idx >> 4, c4 = idx & 15;
        float4 v = *(const float4*)(W + (size_t)(k0 + r) * DD + n0 + c4 * 4);
        tl[r][c4 * 4 + 0] = v.x; tl[r][c4 * 4 + 1] = v.y;
        tl[r][c4 * 4 + 2] = v.z; tl[r][c4 * 4 + 3] = v.w;
    }
    __syncthreads();
    #pragma unroll
    for (int p = 0; p < 4; p++) {
        int idx = tid + p * 256;
        int nl = idx >> 4, kc4 = idx & 15;
        float4 o;
        o.x = f2tf(tl[kc4 * 4 + 0][nl]); o.y = f2tf(tl[kc4 * 4 + 1][nl]);
        o.z = f2tf(tl[kc4 * 4 + 2][nl]); o.w = f2tf(tl[kc4 * 4 + 3][nl]);
        *(float4*)(g_wtf + ((size_t)m * 256 + n0 + nl) * 512 + k0 + kc4 * 4) = o;
    }
}

// ===========================================================================
// attention: S(t) interleaved with PV(t-1) in the same warps; 2 barriers/iter.
// S grid 2x4 (warp 32x16, R12); PV grid 4x2 (warp 64d x 32i, R12).
// P & Kt double-buffered; K single (prefetch in post-interleave zone).
// ===========================================================================
#define A_SU  0        // [2][64] f32
#define A_INV 512      // [64] f32
#define A_LSP 768      // [4][64] f32
#define A_YS  1792     // [64][260] f32
#define A_KS  68352    // [64][260] f32 (single buffer)
#define A_KT  134912   // [2][256][36] u32
#define A_PS  208640   // [2][64][36] u32
#define A_END 227072

__global__ __launch_bounds__(256, 1) void attn_kernel() {
    extern __shared__ char smem[];
    const uint32_t sb = smem_u32(smem);
    float* su_s  = (float*)(smem + A_SU);
    float* inv_s = (float*)(smem + A_INV);
    float* lsp   = (float*)(smem + A_LSP);
    uint32_t* Pw = (uint32_t*)(smem + A_PS);

    const int tid = threadIdx.x, w = tid >> 5, lane = tid & 31;
    const int g = lane >> 2, t = lane & 3;
    const int wsr = w & 1, wsc = w >> 1;      // S grid 2x4
    const int wor = w & 3, woc = w >> 2;      // PV grid 4x2
    const int b = blockIdx.y, q0 = blockIdx.x * BM;
    const int bbase = b * LL;

    const int l7  = lane & 7;
    const int l8h = (lane >> 3) & 1;
    const int l16 = lane >> 4;

    const uint32_t aY0 = sb + A_YS + (uint32_t)(((wsr * 32 + l7 + l8h * 8) * 260 + l16 * 4) * 4);
    const uint32_t aY1 = aY0 + 16 * 260 * 4;
    const uint32_t aKB = sb + A_KS + (uint32_t)(((wsc * 16 + l16 * 8 + l7) * 260 + l8h * 4) * 4);
    const uint32_t aT0 = sb + A_KT + (uint32_t)(((wor * 64 + l7 + l8h * 8) * 36 + l16 * 4) * 4);
    const uint32_t aP0 = sb + A_PS + (uint32_t)(((woc * 32 + l16 * 8 + l7) * 36 + l8h * 4) * 4);

    // ---- preamble: cp.async Y, K(0), Kt(0), su(0) ----
    #pragma unroll
    for (int p = 0; p < 16; p++) {
        int idx = tid + p * 256;
        int r = idx >> 6, c4 = idx & 63;
        cpa16(sb + A_YS + (r * 260 + c4 * 4) * 4,
              &g_yf[((size_t)(bbase + q0 + r)) * DD + c4 * 4]);
    }
    #pragma unroll
    for (int p = 0; p < 16; p++) {
        int idx = tid + p * 256;
        int r = idx >> 6, c4 = idx & 63;
        cpa16(sb + A_KS + (r * 260 + c4 * 4) * 4,
              &g_h[((size_t)(bbase + r)) * 512 + c4 * 4]);
    }
    #pragma unroll
    for (int p = 0; p < 8; p++) {
        int idx = tid + p * 256;
        int d = idx >> 3, c = idx & 7;
        cpa16(sb + A_KT + (d * 36 + c * 4) * 4,
              &g_xT[((size_t)(b * 256 + d)) * 1024 + c * 4]);
    }
    if (tid < 16) cpa16(sb + A_SU + tid * 16, &g_su[bbase + tid * 4]);
    CP_COMMIT();

    float accO[4][4][4];
    #pragma unroll
    for (int mi = 0; mi < 4; mi++)
        #pragma unroll
        for (int ni = 0; ni < 4; ni++)
            #pragma unroll
            for (int q = 0; q < 4; q++) accO[mi][ni][q] = 0.f;
    float lsum[2][2] = {{0.f, 0.f}, {0.f, 0.f}};

    for (int tt = 0; tt < NT; tt++) {
        CP_WAIT0();
        __syncthreads();   // K(tt), Kt(tt), su(tt) ready; P(tt-1) published
        const int buf = tt & 1;
        const int bufC = (tt - 1) & 1;   // PV consumes tile tt-1
        const uint32_t tOfs = aT0 + (uint32_t)(bufC * 36864);
        const uint32_t pOfs = aP0 + (uint32_t)(bufC * 9216);

        // ---- interleaved: S(tt) 32 ks-steps; PV(tt-1) one kj-block per 8 ks ----
        float accS[2][2][4];
        #pragma unroll
        for (int mi = 0; mi < 2; mi++)
            #pragma unroll
            for (int ni = 0; ni < 2; ni++)
                #pragma unroll
                for (int q = 0; q < 4; q++) accS[mi][ni][q] = 0.f;

        #pragma unroll
        for (int ks8 = 0; ks8 < 4; ks8++) {
            #pragma unroll
            for (int ki = 0; ki < 8; ki++) {
                const int ks = ks8 * 8 + ki;
                uint32_t a0[4], a1[4], bq[4];
                ldsm4(a0, aY0 + ks * 32);
                ldsm4(a1, aY1 + ks * 32);
                ldsm4(bq, aKB + ks * 32);
                mma_tf32(accS[0][0], a0, bq);
                mma_tf32(accS[0][1], a0, bq + 2);
                mma_tf32(accS[1][0], a1, bq);
                mma_tf32(accS[1][1], a1, bq + 2);
            }
            if (tt > 0) {   // PV(tt-1), kj = ks8
                const uint32_t jb = (uint32_t)(ks8 * 32);
                uint32_t a[4][4], bp0[4], bp1[4];
                #pragma unroll
                for (int mi = 0; mi < 4; mi++) ldsm4(a[mi], tOfs + mi * 2304 + jb);
                ldsm4(bp0, pOfs + jb);
                ldsm4(bp1, pOfs + 2304 + jb);
                #pragma unroll
                for (int mi = 0; mi < 4; mi++) {
                    mma_bf16(accO[mi][0], a[mi], bp0);
                    mma_bf16(accO[mi][1], a[mi], bp0 + 2);
                    mma_bf16(accO[mi][2], a[mi], bp1);
                    mma_bf16(accO[mi][3], a[mi], bp1 + 2);
                }
            }
        }
        __syncthreads();   // all S reads of K + PV reads of Kt/P(tt-1) done

        // ---- post-interleave: prefetch K(tt+1), Kt(tt+1)->(tt+1)&1, su(tt+1) ----
        if (tt < NT - 1) {
            const int j1 = (tt + 1) * BN;
            #pragma unroll
            for (int p = 0; p < 16; p++) {
                int idx = tid + p * 256;
                int r = idx >> 6, c4 = idx & 63;
                cpa16(sb + A_KS + (r * 260 + c4 * 4) * 4,
                      &g_h[((size_t)(bbase + j1 + r)) * 512 + c4 * 4]);
            }
            #pragma unroll
            for (int p = 0; p < 8; p++) {
                int idx = tid + p * 256;
                int d = idx >> 3, c = idx & 7;
                cpa16(sb + A_KT + ((tt + 1) & 1) * 36864 + (d * 36 + c * 4) * 4,
                      &g_xT[((size_t)(b * 256 + d)) * 1024 + (j1 >> 1) + c * 4]);
            }
            if (tid < 16) cpa16(sb + A_SU + ((tt + 1) & 1) * 256 + tid * 16,
                                &g_su[bbase + j1 + tid * 4]);
            CP_COMMIT();
        }

        // ---- exp epilogue: P(tt) -> buffer tt&1 ----
        #pragma unroll
        for (int mi = 0; mi < 2; mi++)
            #pragma unroll
            for (int ni = 0; ni < 2; ni++) {
                const int c01 = wsc * 16 + ni * 8 + 2 * t;
                const float s0 = su_s[buf * 64 + c01], s1 = su_s[buf * 64 + c01 + 1];
                float p0 = __expf(accS[mi][ni][0] + s0);
                float p1 = __expf(accS[mi][ni][1] + s1);
                float p2 = __expf(accS[mi][ni][2] + s0);
                float p3 = __expf(accS[mi][ni][3] + s1);
                lsum[mi][0] += p0 + p1;
                lsum[mi][1] += p2 + p3;
                const int row = wsr * 32 + mi * 16 + g;
                const int jw = wsc * 8 + ni * 4 + t;
                Pw[buf * 2304 + row * 36 + jw]       = pk(p0, p1);
                Pw[buf * 2304 + (row + 8) * 36 + jw] = pk(p2, p3);
            }
    }

    // ---- drain: PV(NT-1) ----
    __syncthreads();   // P(NT-1) published
    {
        const int bufC = (NT - 1) & 1;
        const uint32_t tOfs = aT0 + (uint32_t)(bufC * 36864);
        const uint32_t pOfs = aP0 + (uint32_t)(bufC * 9216);
        #pragma unroll
        for (int kj = 0; kj < 4; kj++) {
            const uint32_t jb = (uint32_t)(kj * 32);
            uint32_t a[4][4], bp0[4], bp1[4];
            #pragma unroll
            for (int mi = 0; mi < 4; mi++) ldsm4(a[mi], tOfs + mi * 2304 + jb);
            ldsm4(bp0, pOfs + jb);
            ldsm4(bp1, pOfs + 2304 + jb);
            #pragma unroll
            for (int mi = 0; mi < 4; mi++) {
                mma_bf16(accO[mi][0], a[mi], bp0);
                mma_bf16(accO[mi][1], a[mi], bp0 + 2);
                mma_bf16(accO[mi][2], a[mi], bp1);
                mma_bf16(accO[mi][3], a[mi], bp1 + 2);
            }
        }
    }

    // ---- row-sum reduce ----
    #pragma unroll
    for (int mi = 0; mi < 2; mi++)
        #pragma unroll
        for (int rh = 0; rh < 2; rh++) {
            float v = lsum[mi][rh];
            v += __shfl_xor_sync(0xffffffffu, v, 1);
            v += __shfl_xor_sync(0xffffffffu, v, 2);
            if (t == 0) lsp[wsc * 64 + wsr * 32 + mi * 16 + rh * 8 + g] = v;
        }
    __syncthreads();
    if (tid < 64)
        inv_s[tid] = 1.f / (lsp[tid] + lsp[64 + tid] + lsp[128 + tid] + lsp[192 + tid]);
    __syncthreads();

    // ---- normalize, tf32-round, transpose via shfl, store to g_h ----
    const bool even = ((g & 1) == 0);
    #pragma unroll
    for (int mi = 0; mi < 4; mi++)
        #pragma unroll
        for (int ni = 0; ni < 4; ni++) {
            const int iA = woc * 32 + ni * 8 + 2 * t;
            const float invA = inv_s[iA], invB = inv_s[iA + 1];
            float c0 = f2tf(accO[mi][ni][0] * invA), c1 = f2tf(accO[mi][ni][1] * invB);
            float c2 = f2tf(accO[mi][ni][2] * invA), c3 = f2tf(accO[mi][ni][3] * invB);
            float v0 = __shfl_xor_sync(0xffffffffu, c0, 4);
            float v1 = __shfl_xor_sync(0xffffffffu, c1, 4);
            float v2 = __shfl_xor_sync(0xffffffffu, c2, 4);
            float v3 = __shfl_xor_sync(0xffffffffu, c3, 4);
            float* rowA = g_h + ((size_t)(bbase + q0 + iA)) * 512 + 256;
            float* rowB = rowA + 512;
            if (even) {
                const int d2 = (wor * 32 + mi * 8 + (g >> 1)) * 2;
                *(float2*)(rowA + d2) = make_float2(c0, v0);
                *(float2*)(rowB + d2) = make_float2(c1, v1);
            } else {
                const int d2 = (wor * 32 + mi * 8 + ((g + 7) >> 1)) * 2;
                *(float2*)(rowA + d2) = make_float2(v2, c2);
                *(float2*)(rowB + d2) = make_float2(v3, c3);
            }
        }
}

// ===========================================================================
// MLP tf32 (unchanged from R12): grid (128, 4), 256 thr, ldmatrix frags.
// ===========================================================================
#define M_HS 0
#define M_WS 36864
#define M_END 92160

__global__ __launch_bounds__(256, 1)
void mlp_kernel(const float* __restrict__ x,
                const float* __restrict__ b1, const float* __restrict__ b2,
                const float* __restrict__ b3, float* __restrict__ out)
{
    extern __shared__ char smem[];
    const uint32_t sb = smem_u32(smem);

    const int tid = threadIdx.x, w = tid >> 5, lane = tid & 31;
    const int g = lane >> 2, t = lane & 3;
    const int mw = w >> 1, nw = w & 1;
    const int row0 = blockIdx.x * 128, n0 = blockIdx.y * 64;

    const int l7  = lane & 7;
    const int l8h = (lane >> 3) & 1;
    const int l16 = lane >> 4;
    const uint32_t aH0 = sb + M_HS + (uint32_t)(((mw * 32 + l7 + l8h * 8) * 36 + l16 * 4) * 4);
    const uint32_t aW0 = sb + M_WS + (uint32_t)(((nw * 32 + l16 * 8 + l7) * 36 + l8h * 4) * 4);

    #pragma unroll
    for (int p = 0; p < 4; p++) {
        int idx = tid + p * 256;
        int r = idx >> 3, c = idx & 7;
        cpa16(sb + M_HS + (r * 36 + c * 4) * 4,
              &g_h[((size_t)(row0 + r)) * 512 + c * 4]);
    }
    #pragma unroll
    for (int p = 0; p < 6; p++) {
        int idx = tid + p * 256;
        int m = idx >> 9, rem = idx & 511;
        int n = rem >> 3, c = rem & 7;
        cpa16(sb + M_WS + ((m * 64 + n) * 36 + c * 4) * 4,
              &g_wtf[((size_t)m * 256 + n0 + n) * 512 + c * 4]);
    }
    CP_COMMIT();

    float acc[3][2][4][4];
    #pragma unroll
    for (int m = 0; m < 3; m++)
        #pragma unroll
        for (int mi = 0; mi < 2; mi++)
            #pragma unroll
            for (int ni = 0; ni < 4; ni++)
                #pragma unroll
                for (int q = 0; q < 4; q++) acc[m][mi][ni][q] = 0.f;

    for (int s = 0; s < 16; s++) {
        CP_WAIT0();
        __syncthreads();
        const int buf = s & 1;

        if (s < 15) {
            const int nb = (s + 1) & 1, k1 = (s + 1) * 32;
            #pragma unroll
            for (int p = 0; p < 4; p++) {
                int idx = tid + p * 256;
                int r = idx >> 3, c = idx & 7;
                cpa16(sb + M_HS + nb * 18432 + (r * 36 + c * 4) * 4,
                      &g_h[((size_t)(row0 + r)) * 512 + k1 + c * 4]);
            }
            #pragma unroll
            for (int p = 0; p < 6; p++) {
                int idx = tid + p * 256;
                int m = idx >> 9, rem = idx & 511;
                int n = rem >> 3, c = rem & 7;
                cpa16(sb + M_WS + nb * 27648 + ((m * 64 + n) * 36 + c * 4) * 4,
                      &g_wtf[((size_t)m * 256 + n0 + n) * 512 + k1 + c * 4]);
            }
            CP_COMMIT();
        }

        const uint32_t hOfs = aH0 + (uint32_t)(buf * 18432);
        const uint32_t wOfs = aW0 + (uint32_t)(buf * 27648);
        #pragma unroll
        for (int ks = 0; ks < 4; ks++) {
            const uint32_t kb = (uint32_t)(ks * 32);
            uint32_t a0[4], a1[4];
            ldsm4(a0, hOfs + kb);
            ldsm4(a1, hOfs + 16 * 36 * 4 + kb);
            #pragma unroll
            for (int m = 0; m < 3; m++) {
                uint32_t bq0[4], bq1[4];
                ldsm4(bq0, wOfs + m * 9216 + kb);
                ldsm4(bq1, wOfs + m * 9216 + 2304 + kb);
                mma_tf32(acc[m][0][0], a0, bq0);
                mma_tf32(acc[m][0][1], a0, bq0 + 2);
                mma_tf32(acc[m][0][2], a0, bq1);
                mma_tf32(acc[m][0][3], a0, bq1 + 2);
                mma_tf32(acc[m][1][0], a1, bq0);
                mma_tf32(acc[m][1][1], a1, bq0 + 2);
                mma_tf32(acc[m][1][2], a1, bq1);
                mma_tf32(acc[m][1][3], a1, bq1 + 2);
            }
        }
    }

    #pragma unroll
    for (int mi = 0; mi < 2; mi++)
        #pragma unroll
        for (int ni = 0; ni < 4; ni++) {
            const int rloc = mw * 32 + mi * 16 + g;
            const int cc = n0 + nw * 32 + ni * 8 + 2 * t;
            const float2 bb1 = *(const float2*)(b1 + cc);
            const float2 bb2 = *(const float2*)(b2 + cc);
            const float2 bb3 = *(const float2*)(b3 + cc);
            #pragma unroll
            for (int h = 0; h < 2; h++) {
                const int rl = rloc + h * 8, i0 = h * 2;
                float z0 = tanhf(acc[0][mi][ni][i0]     + bb1.x);
                float z1 = tanhf(acc[0][mi][ni][i0 + 1] + bb1.y);
                float r0 = 1.f / (1.f + __expf(-(acc[1][mi][ni][i0]     + bb2.x)));
                float r1 = 1.f / (1.f + __expf(-(acc[1][mi][ni][i0 + 1] + bb2.y)));
                float f0 = 1.f / (1.f + __expf(-(acc[2][mi][ni][i0]     + bb3.x)));
                float f1 = 1.f / (1.f + __expf(-(acc[2][mi][ni][i0 + 1] + bb3.y)));
                const float2 xv = *(const float2*)(x + (size_t)(row0 + rl) * DD + cc);
                float2 o = make_float2(r0 * xv.x + f0 * z0, r1 * xv.y + f1 * z1);
                *(float2*)(out + (size_t)(row0 + rl) * DD + cc) = o;
            }
        }
}

// ===========================================================================
extern "C" void kernel_launch(void* const* d_in, const int* in_sizes, int n_in,
                              void* d_out, int out_size)
{
    const float* x   = (const float*)d_in[0];
    const float* wia = (const float*)d_in[1];
    const float* w1  = (const float*)d_in[2];
    const float* w2  = (const float*)d_in[3];
    const float* w3  = (const float*)d_in[4];
    const float* b1  = (const float*)d_in[5];
    const float* b2  = (const float*)d_in[6];
    const float* b3  = (const float*)d_in[7];
    float* out = (float*)d_out;

    cudaFuncSetAttribute(attn_kernel, cudaFuncAttributeMaxDynamicSharedMemorySize, A_END);
    cudaFuncSetAttribute(mlp_kernel,  cudaFuncAttributeMaxDynamicSharedMemorySize, M_END);

    prep_su  <<<LL * BB / 8, 256>>>(x, wia);
    prep_pack<<<BB * 128, 256>>>(x, wia);
    prep_w   <<<96, 256>>>(w1, w2, w3);
    attn_kernel<<<dim3(LL / BM, BB), 256, A_END>>>();
    mlp_kernel <<<dim3(BB * LL / 128, 4), 256, M_END>>>(x, b1, b2, b3, out);
}

// round 16
// speedup vs baseline: 1.1658x; 1.0293x over previous
#include <cuda_runtime.h>
#include <cstdint>

#define BB 8
#define LL 2048
#define DD 256
#define BM 64
#define BN 64
#define NT (LL / BN)

// ---- global scratch (allocation-free device arrays) ----
__device__ float    g_yf[(size_t)BB * LL * DD];     // tf32(x*wp)
__device__ float    g_h [(size_t)BB * LL * 512];    // [tf32(x) | tf32(attn)]
__device__ uint32_t g_xT[(size_t)BB * 256 * 1024];  // x^T bf16 j-pairs
__device__ float    g_su[(size_t)BB * LL];
__device__ float    g_wtf[3 * 256 * 512];           // W^T tf32 [m][n][k]

// ---- helpers ----
__device__ __forceinline__ uint32_t smem_u32(const void* p) {
    uint32_t a;
    asm("{ .reg .u64 t; cvta.to.shared.u64 t, %1; cvt.u32.u64 %0, t; }" : "=r"(a) : "l"(p));
    return a;
}
__device__ __forceinline__ uint32_t pk(float lo, float hi) {
    uint32_t r; asm("cvt.rn.bf16x2.f32 %0, %1, %2;" : "=r"(r) : "f"(hi), "f"(lo)); return r;
}
__device__ __forceinline__ float bf_lo(uint32_t u) { return __uint_as_float(u << 16); }
__device__ __forceinline__ float bf_hi(uint32_t u) { return __uint_as_float(u & 0xffff0000u); }
__device__ __forceinline__ float f2tf(float f) {
    uint32_t u; asm("cvt.rna.tf32.f32 %0, %1;" : "=r"(u) : "f"(f)); return __uint_as_float(u);
}
__device__ __forceinline__ void cpa16(uint32_t dst, const void* src) {
    asm volatile("cp.async.ca.shared.global [%0], [%1], 16;" :: "r"(dst), "l"(src));
}
#define CP_COMMIT() asm volatile("cp.async.commit_group;")
#define CP_WAIT0()  asm volatile("cp.async.wait_group 0;")

__device__ __forceinline__ void ldsm4(uint32_t* r, uint32_t addr) {
    asm volatile("ldmatrix.sync.aligned.m8n8.x4.shared.b16 {%0,%1,%2,%3}, [%4];"
        : "=r"(r[0]), "=r"(r[1]), "=r"(r[2]), "=r"(r[3]) : "r"(addr));
}
__device__ __forceinline__ void mma_bf16(float* c, const uint32_t* a, const uint32_t* b) {
    asm volatile("mma.sync.aligned.m16n8k16.row.col.f32.bf16.bf16.f32 "
        "{%0,%1,%2,%3}, {%4,%5,%6,%7}, {%8,%9}, {%0,%1,%2,%3};"
        : "+f"(c[0]), "+f"(c[1]), "+f"(c[2]), "+f"(c[3])
        : "r"(a[0]), "r"(a[1]), "r"(a[2]), "r"(a[3]), "r"(b[0]), "r"(b[1]));
}
__device__ __forceinline__ void mma_tf32(float* c, const uint32_t* a, const uint32_t* b) {
    asm volatile("mma.sync.aligned.m16n8k8.row.col.f32.tf32.tf32.f32 "
        "{%0,%1,%2,%3}, {%4,%5,%6,%7}, {%8,%9}, {%0,%1,%2,%3};"
        : "+f"(c[0]), "+f"(c[1]), "+f"(c[2]), "+f"(c[3])
        : "r"(a[0]), "r"(a[1]), "r"(a[2]), "r"(a[3]), "r"(b[0]), "r"(b[1]));
}

// ===========================================================================
// prep kernels (unchanged)
// ===========================================================================
__global__ void prep_su(const float* __restrict__ x, const float* __restrict__ w_itr) {
    int row = blockIdx.x * 8 + (threadIdx.x >> 5);
    int lane = threadIdx.x & 31;
    const float* xr = x + (size_t)row * DD;
    float s = 0.f;
    #pragma unroll
    for (int k = 0; k < 8; k++) s += xr[lane + 32 * k] * w_itr[lane + 32 * k];
    #pragma unroll
    for (int off = 16; off > 0; off >>= 1) s += __shfl_xor_sync(0xffffffffu, s, off);
    if (lane == 0) g_su[row] = s;
}

__global__ void prep_pack(const float* __restrict__ x, const float* __restrict__ w_itr) {
    __shared__ float tl[64][65];
    int blk = blockIdx.x;
    int b = blk >> 7, rem = blk & 127, jt = rem >> 2, dt = rem & 3;
    int j0 = jt * 64, d0 = dt * 64;
    const float* xb = x + ((size_t)b * LL + j0) * DD + d0;
    int tid = threadIdx.x;
    #pragma unroll
    for (int p = 0; p < 4; p++) {
        int idx = tid + p * 256;
        int r = idx >> 4, c4 = idx & 15;
        float4 v = *(const float4*)(xb + (size_t)r * DD + c4 * 4);
        tl[r][c4 * 4 + 0] = v.x; tl[r][c4 * 4 + 1] = v.y;
        tl[r][c4 * 4 + 2] = v.z; tl[r][c4 * 4 + 3] = v.w;
    }
    __syncthreads();
    const float* wp = w_itr + 2 * DD;
    #pragma unroll
    for (int p = 0; p < 4; p++) {
        int idx = tid + p * 256;
        int r = idx >> 4, c4 = idx & 15;
        float a0 = tl[r][c4 * 4 + 0], a1 = tl[r][c4 * 4 + 1];
        float a2 = tl[r][c4 * 4 + 2], a3 = tl[r][c4 * 4 + 3];
        float4 y, h;
        y.x = f2tf(a0 * wp[d0 + c4 * 4 + 0]); y.y = f2tf(a1 * wp[d0 + c4 * 4 + 1]);
        y.z = f2tf(a2 * wp[d0 + c4 * 4 + 2]); y.w = f2tf(a3 * wp[d0 + c4 * 4 + 3]);
        h.x = f2tf(a0); h.y = f2tf(a1); h.z = f2tf(a2); h.w = f2tf(a3);
        *(float4*)(g_yf + ((size_t)b * LL + j0 + r) * DD + d0 + c4 * 4) = y;
        *(float4*)(g_h  + ((size_t)b * LL + j0 + r) * 512 + d0 + c4 * 4) = h;
    }
    #pragma unroll
    for (int p = 0; p < 8; p++) {
        int idx = tid + p * 256;
        int dl = idx >> 5, jw = idx & 31;
        g_xT[((size_t)b * 256 + d0 + dl) * 1024 + (j0 >> 1) + jw] =
            pk(tl[2 * jw][dl], tl[2 * jw + 1][dl]);
    }
}

__global__ void prep_w(const float* __restrict__ w1, const float* __restrict__ w2,
                       const float* __restrict__ w3) {
    __shared__ float tl[64][65];
    int blk = blockIdx.x;
    int m = blk >> 5, rem = blk & 31, kt = rem >> 2, nt = rem & 3;
    int k0 = kt * 64, n0 = nt * 64;
    const float* W = (m == 0) ? w1 : (m == 1) ? w2 : w3;
    int tid = threadIdx.x;
    #pragma unroll
    for (int p = 0; p < 4; p++) {
        int idx = tid + p * 256;
        int r = idx >> 4, c4 = idx & 15;
        float4 v = *(const float4*)(W + (size_t)(k0 + r) * DD + n0 + c4 * 4);
        tl[r][c4 * 4 + 0] = v.x; tl[r][c4 * 4 + 1] = v.y;
        tl[r][c4 * 4 + 2] = v.z; tl[r][c4 * 4 + 3] = v.w;
    }
    __syncthreads();
    #pragma unroll
    for (int p = 0; p < 4; p++) {
        int idx = tid + p * 256;
        int nl = idx >> 4, kc4 = idx & 15;
        float4 o;
        o.x = f2tf(tl[kc4 * 4 + 0][nl]); o.y = f2tf(tl[kc4 * 4 + 1][nl]);
        o.z = f2tf(tl[kc4 * 4 + 2][nl]); o.w = f2tf(tl[kc4 * 4 + 3][nl]);
        *(float4*)(g_wtf + ((size_t)m * 256 + n0 + nl) * 512 + k0 + kc4 * 4) = o;
    }
}

// ===========================================================================
// attention: d-split S (exp-product combine, Pa aliased into P buffer)
// interleaved with PV(t-1). Roles: i2=w&1, j2=(w>>1)&1, kh=w>>2.
// PV grid: wor=w&3 (d-block), woc=w>>2. 2 barriers/iter.
// ===========================================================================
#define A_SU  0        // [2][64] f32
#define A_INV 512      // [64] f32
#define A_LSP 768      // [2][64] f32
#define A_YS  1792     // [64][260] f32
#define A_KS  68352    // [64][260] f32 (single buffer)
#define A_KT  134912   // [2][256][36] u32
#define A_PS  208640   // [2][64][36] u32 (Pa aliased into parity tt&1)
#define A_END 227072

__global__ __launch_bounds__(256, 1) void attn_kernel() {
    extern __shared__ char smem[];
    const uint32_t sb = smem_u32(smem);
    float* su_s  = (float*)(smem + A_SU);
    float* inv_s = (float*)(smem + A_INV);
    float* lsp   = (float*)(smem + A_LSP);
    uint32_t* Pw = (uint32_t*)(smem + A_PS);

    const int tid = threadIdx.x, w = tid >> 5, lane = tid & 31;
    const int g = lane >> 2, t = lane & 3;
    const int i2 = w & 1, j2 = (w >> 1) & 1, kh = w >> 2;   // S roles
    const int wor = w & 3, woc = w >> 2;                    // PV grid 4x2
    const int b = blockIdx.y, q0 = blockIdx.x * BM;
    const int bbase = b * LL;

    const int l7  = lane & 7;
    const int l8h = (lane >> 3) & 1;
    const int l16 = lane >> 4;

    // S-phase bases (d offset kh*128 words)
    const uint32_t aY0 = sb + A_YS +
        (uint32_t)(((i2 * 32 + l7 + l8h * 8) * 260 + l16 * 4 + kh * 128) * 4);
    const uint32_t aY1 = aY0 + 16 * 260 * 4;
    const uint32_t aKB0 = sb + A_KS +
        (uint32_t)(((j2 * 32 + l16 * 8 + l7) * 260 + l8h * 4 + kh * 128) * 4);
    const uint32_t aKB1 = aKB0 + 16 * 260 * 4;
    // PV bases
    const uint32_t aT0 = sb + A_KT + (uint32_t)(((wor * 64 + l7 + l8h * 8) * 36 + l16 * 4) * 4);
    const uint32_t aP0 = sb + A_PS + (uint32_t)(((woc * 32 + l16 * 8 + l7) * 36 + l8h * 4) * 4);

    // ---- preamble: cp.async Y, K(0), Kt(0), su(0) (all threads) ----
    #pragma unroll
    for (int p = 0; p < 16; p++) {
        int idx = tid + p * 256;
        int r = idx >> 6, c4 = idx & 63;
        cpa16(sb + A_YS + (r * 260 + c4 * 4) * 4,
              &g_yf[((size_t)(bbase + q0 + r)) * DD + c4 * 4]);
    }
    #pragma unroll
    for (int p = 0; p < 16; p++) {
        int idx = tid + p * 256;
        int r = idx >> 6, c4 = idx & 63;
        cpa16(sb + A_KS + (r * 260 + c4 * 4) * 4,
              &g_h[((size_t)(bbase + r)) * 512 + c4 * 4]);
    }
    #pragma unroll
    for (int p = 0; p < 8; p++) {
        int idx = tid + p * 256;
        int d = idx >> 3, c = idx & 7;
        cpa16(sb + A_KT + (d * 36 + c * 4) * 4,
              &g_xT[((size_t)(b * 256 + d)) * 1024 + c * 4]);
    }
    if (tid < 16) cpa16(sb + A_SU + tid * 16, &g_su[bbase + tid * 4]);
    CP_COMMIT();

    float accO[4][4][4];
    #pragma unroll
    for (int mi = 0; mi < 4; mi++)
        #pragma unroll
        for (int ni = 0; ni < 4; ni++)
            #pragma unroll
            for (int q = 0; q < 4; q++) accO[mi][ni][q] = 0.f;
    float lsum[2][2] = {{0.f, 0.f}, {0.f, 0.f}};

    for (int tt = 0; tt < NT; tt++) {
        CP_WAIT0();
        __syncthreads();   // K(tt), Kt(tt), su(tt) ready; P(tt-1) published
        const int buf = tt & 1;
        const int bufC = (tt - 1) & 1;
        const uint32_t tOfs = aT0 + (uint32_t)(bufC * 36864);
        const uint32_t pOfs = aP0 + (uint32_t)(bufC * 9216);

        // ---- interleaved: S-partial (16 ks, this warp's d-half) + PV(tt-1) ----
        float accS[2][4][4];
        #pragma unroll
        for (int mi = 0; mi < 2; mi++)
            #pragma unroll
            for (int ni = 0; ni < 4; ni++)
                #pragma unroll
                for (int q = 0; q < 4; q++) accS[mi][ni][q] = 0.f;

        #pragma unroll
        for (int ks4 = 0; ks4 < 4; ks4++) {
            #pragma unroll
            for (int ki = 0; ki < 4; ki++) {
                const int ks = ks4 * 4 + ki;
                uint32_t a0[4], a1[4], bq0[4], bq1[4];
                ldsm4(a0, aY0 + ks * 32);
                ldsm4(a1, aY1 + ks * 32);
                ldsm4(bq0, aKB0 + ks * 32);
                ldsm4(bq1, aKB1 + ks * 32);
                mma_tf32(accS[0][0], a0, bq0); mma_tf32(accS[0][1], a0, bq0 + 2);
                mma_tf32(accS[0][2], a0, bq1); mma_tf32(accS[0][3], a0, bq1 + 2);
                mma_tf32(accS[1][0], a1, bq0); mma_tf32(accS[1][1], a1, bq0 + 2);
                mma_tf32(accS[1][2], a1, bq1); mma_tf32(accS[1][3], a1, bq1 + 2);
            }
            if (tt > 0) {   // PV(tt-1), kj = ks4
                const uint32_t jb = (uint32_t)(ks4 * 32);
                uint32_t a[4][4], bp0[4], bp1[4];
                #pragma unroll
                for (int mi = 0; mi < 4; mi++) ldsm4(a[mi], tOfs + mi * 2304 + jb);
                ldsm4(bp0, pOfs + jb);
                ldsm4(bp1, pOfs + 2304 + jb);
                #pragma unroll
                for (int mi = 0; mi < 4; mi++) {
                    mma_bf16(accO[mi][0], a[mi], bp0);
                    mma_bf16(accO[mi][1], a[mi], bp0 + 2);
                    mma_bf16(accO[mi][2], a[mi], bp1);
                    mma_bf16(accO[mi][3], a[mi], bp1 + 2);
                }
            }
        }

        // ---- kh0: Pa = bf16(exp(S1)) -> P[buf] (aliased) ----
        if (kh == 0) {
            #pragma unroll
            for (int mi = 0; mi < 2; mi++)
                #pragma unroll
                for (int ni = 0; ni < 4; ni++) {
                    const int row = i2 * 32 + mi * 16 + g;
                    const int jw = j2 * 16 + ni * 4 + t;
                    float p0 = __expf(accS[mi][ni][0]);
                    float p1 = __expf(accS[mi][ni][1]);
                    float p2 = __expf(accS[mi][ni][2]);
                    float p3 = __expf(accS[mi][ni][3]);
                    Pw[buf * 2304 + row * 36 + jw]       = pk(p0, p1);
                    Pw[buf * 2304 + (row + 8) * 36 + jw] = pk(p2, p3);
                }
        }
        __syncthreads();   // Pa visible; S + PV(tt-1) reads all done

        if (kh == 1) {
            // ---- kh1: P[buf] = Pa * exp(S2 + su), lsum ----
            #pragma unroll
            for (int mi = 0; mi < 2; mi++)
                #pragma unroll
                for (int ni = 0; ni < 4; ni++) {
                    const int c01 = j2 * 32 + ni * 8 + 2 * t;
                    const float s0 = su_s[buf * 64 + c01], s1 = su_s[buf * 64 + c01 + 1];
                    const int row = i2 * 32 + mi * 16 + g;
                    const int jw = j2 * 16 + ni * 4 + t;
                    const uint32_t ua = Pw[buf * 2304 + row * 36 + jw];
                    const uint32_t ub = Pw[buf * 2304 + (row + 8) * 36 + jw];
                    float q0 = __expf(accS[mi][ni][0] + s0) * bf_lo(ua);
                    float q1 = __expf(accS[mi][ni][1] + s1) * bf_hi(ua);
                    float q2 = __expf(accS[mi][ni][2] + s0) * bf_lo(ub);
                    float q3 = __expf(accS[mi][ni][3] + s1) * bf_hi(ub);
                    lsum[mi][0] += q0 + q1;
                    lsum[mi][1] += q2 + q3;
                    Pw[buf * 2304 + row * 36 + jw]       = pk(q0, q1);
                    Pw[buf * 2304 + (row + 8) * 36 + jw] = pk(q2, q3);
                }
        } else if (tt < NT - 1) {
            // ---- kh0 warps: prefetch K(t+1), Kt(t+1), su(t+1) ----
            const int j1 = (tt + 1) * BN;
            #pragma unroll
            for (int p = 0; p < 32; p++) {
                int idx = tid + p * 128;
                int r = idx >> 6, c4 = idx & 63;
                cpa16(sb + A_KS + (r * 260 + c4 * 4) * 4,
                      &g_h[((size_t)(bbase + j1 + r)) * 512 + c4 * 4]);
            }
            #pragma unroll
            for (int p = 0; p < 16; p++) {
                int idx = tid + p * 128;
                int d = idx >> 3, c = idx & 7;
                cpa16(sb + A_KT + ((tt + 1) & 1) * 36864 + (d * 36 + c * 4) * 4,
                      &g_xT[((size_t)(b * 256 + d)) * 1024 + (j1 >> 1) + c * 4]);
            }
            if (tid < 16) cpa16(sb + A_SU + ((tt + 1) & 1) * 256 + tid * 16,
                                &g_su[bbase + j1 + tid * 4]);
            CP_COMMIT();
        }
        // next loop-top: CP_WAIT0 (issuers) + __syncthreads publishes everything
    }

    // ---- drain: PV(NT-1) ----
    __syncthreads();
    {
        const int bufC = (NT - 1) & 1;
        const uint32_t tOfs = aT0 + (uint32_t)(bufC * 36864);
        const uint32_t pOfs = aP0 + (uint32_t)(bufC * 9216);
        #pragma unroll
        for (int kj = 0; kj < 4; kj++) {
            const uint32_t jb = (uint32_t)(kj * 32);
            uint32_t a[4][4], bp0[4], bp1[4];
            #pragma unroll
            for (int mi = 0; mi < 4; mi++) ldsm4(a[mi], tOfs + mi * 2304 + jb);
            ldsm4(bp0, pOfs + jb);
            ldsm4(bp1, pOfs + 2304 + jb);
            #pragma unroll
            for (int mi = 0; mi < 4; mi++) {
                mma_bf16(accO[mi][0], a[mi], bp0);
                mma_bf16(accO[mi][1], a[mi], bp0 + 2);
                mma_bf16(accO[mi][2], a[mi], bp1);
                mma_bf16(accO[mi][3], a[mi], bp1 + 2);
            }
        }
    }

    // ---- lsum reduce (kh1 warps hold sums; 2 j2 groups) ----
    if (kh == 1) {
        #pragma unroll
        for (int mi = 0; mi < 2; mi++)
            #pragma unroll
            for (int rh = 0; rh < 2; rh++) {
                float v = lsum[mi][rh];
                v += __shfl_xor_sync(0xffffffffu, v, 1);
                v += __shfl_xor_sync(0xffffffffu, v, 2);
                if (t == 0) lsp[j2 * 64 + i2 * 32 + mi * 16 + rh * 8 + g] = v;
            }
    }
    __syncthreads();
    if (tid < 64) inv_s[tid] = 1.f / (lsp[tid] + lsp[64 + tid]);
    __syncthreads();

    // ---- normalize, tf32-round, transpose via shfl, store to g_h ----
    const bool even = ((g & 1) == 0);
    #pragma unroll
    for (int mi = 0; mi < 4; mi++)
        #pragma unroll
        for (int ni = 0; ni < 4; ni++) {
            const int iA = woc * 32 + ni * 8 + 2 * t;
            const float invA = inv_s[iA], invB = inv_s[iA + 1];
            float c0 = f2tf(accO[mi][ni][0] * invA), c1 = f2tf(accO[mi][ni][1] * invB);
            float c2 = f2tf(accO[mi][ni][2] * invA), c3 = f2tf(accO[mi][ni][3] * invB);
            float v0 = __shfl_xor_sync(0xffffffffu, c0, 4);
            float v1 = __shfl_xor_sync(0xffffffffu, c1, 4);
            float v2 = __shfl_xor_sync(0xffffffffu, c2, 4);
            float v3 = __shfl_xor_sync(0xffffffffu, c3, 4);
            float* rowA = g_h + ((size_t)(bbase + q0 + iA)) * 512 + 256;
            float* rowB = rowA + 512;
            if (even) {
                const int d2 = (wor * 32 + mi * 8 + (g >> 1)) * 2;
                *(float2*)(rowA + d2) = make_float2(c0, v0);
                *(float2*)(rowB + d2) = make_float2(c1, v1);
            } else {
                const int d2 = (wor * 32 + mi * 8 + ((g + 7) >> 1)) * 2;
                *(float2*)(rowA + d2) = make_float2(v2, c2);
                *(float2*)(rowB + d2) = make_float2(v3, c3);
            }
        }
}

// ===========================================================================
// MLP tf32 (unchanged from R12/R15): grid (128, 4), 256 thr, ldmatrix frags.
// ===========================================================================
#define M_HS 0
#define M_WS 36864
#define M_END 92160

__global__ __launch_bounds__(256, 1)
void mlp_kernel(const float* __restrict__ x,
                const float* __restrict__ b1, const float* __restrict__ b2,
                const float* __restrict__ b3, float* __restrict__ out)
{
    extern __shared__ char smem[];
    const uint32_t sb = smem_u32(smem);

    const int tid = threadIdx.x, w = tid >> 5, lane = tid & 31;
    const int g = lane >> 2, t = lane & 3;
    const int mw = w >> 1, nw = w & 1;
    const int row0 = blockIdx.x * 128, n0 = blockIdx.y * 64;

    const int l7  = lane & 7;
    const int l8h = (lane >> 3) & 1;
    const int l16 = lane >> 4;
    const uint32_t aH0 = sb + M_HS + (uint32_t)(((mw * 32 + l7 + l8h * 8) * 36 + l16 * 4) * 4);
    const uint32_t aW0 = sb + M_WS + (uint32_t)(((nw * 32 + l16 * 8 + l7) * 36 + l8h * 4) * 4);

    #pragma unroll
    for (int p = 0; p < 4; p++) {
        int idx = tid + p * 256;
        int r = idx >> 3, c = idx & 7;
        cpa16(sb + M_HS + (r * 36 + c * 4) * 4,
              &g_h[((size_t)(row0 + r)) * 512 + c * 4]);
    }
    #pragma unroll
    for (int p = 0; p < 6; p++) {
        int idx = tid + p * 256;
        int m = idx >> 9, rem = idx & 511;
        int n = rem >> 3, c = rem & 7;
        cpa16(sb + M_WS + ((m * 64 + n) * 36 + c * 4) * 4,
              &g_wtf[((size_t)m * 256 + n0 + n) * 512 + c * 4]);
    }
    CP_COMMIT();

    float acc[3][2][4][4];
    #pragma unroll
    for (int m = 0; m < 3; m++)
        #pragma unroll
        for (int mi = 0; mi < 2; mi++)
            #pragma unroll
            for (int ni = 0; ni < 4; ni++)
                #pragma unroll
                for (int q = 0; q < 4; q++) acc[m][mi][ni][q] = 0.f;

    for (int s = 0; s < 16; s++) {
        CP_WAIT0();
        __syncthreads();
        const int buf = s & 1;

        if (s < 15) {
            const int nb = (s + 1) & 1, k1 = (s + 1) * 32;
            #pragma unroll
            for (int p = 0; p < 4; p++) {
                int idx = tid + p * 256;
                int r = idx >> 3, c = idx & 7;
                cpa16(sb + M_HS + nb * 18432 + (r * 36 + c * 4) * 4,
                      &g_h[((size_t)(row0 + r)) * 512 + k1 + c * 4]);
            }
            #pragma unroll
            for (int p = 0; p < 6; p++) {
                int idx = tid + p * 256;
                int m = idx >> 9, rem = idx & 511;
                int n = rem >> 3, c = rem & 7;
                cpa16(sb + M_WS + nb * 27648 + ((m * 64 + n) * 36 + c * 4) * 4,
                      &g_wtf[((size_t)m * 256 + n0 + n) * 512 + k1 + c * 4]);
            }
            CP_COMMIT();
        }

        const uint32_t hOfs = aH0 + (uint32_t)(buf * 18432);
        const uint32_t wOfs = aW0 + (uint32_t)(buf * 27648);
        #pragma unroll
        for (int ks = 0; ks < 4; ks++) {
            const uint32_t kb = (uint32_t)(ks * 32);
            uint32_t a0[4], a1[4];
            ldsm4(a0, hOfs + kb);
            ldsm4(a1, hOfs + 16 * 36 * 4 + kb);
            #pragma unroll
            for (int m = 0; m < 3; m++) {
                uint32_t bq0[4], bq1[4];
                ldsm4(bq0, wOfs + m * 9216 + kb);
                ldsm4(bq1, wOfs + m * 9216 + 2304 + kb);
                mma_tf32(acc[m][0][0], a0, bq0);
                mma_tf32(acc[m][0][1], a0, bq0 + 2);
                mma_tf32(acc[m][0][2], a0, bq1);
                mma_tf32(acc[m][0][3], a0, bq1 + 2);
                mma_tf32(acc[m][1][0], a1, bq0);
                mma_tf32(acc[m][1][1], a1, bq0 + 2);
                mma_tf32(acc[m][1][2], a1, bq1);
                mma_tf32(acc[m][1][3], a1, bq1 + 2);
            }
        }
    }

    #pragma unroll
    for (int mi = 0; mi < 2; mi++)
        #pragma unroll
        for (int ni = 0; ni < 4; ni++) {
            const int rloc = mw * 32 + mi * 16 + g;
            const int cc = n0 + nw * 32 + ni * 8 + 2 * t;
            const float2 bb1 = *(const float2*)(b1 + cc);
            const float2 bb2 = *(const float2*)(b2 + cc);
            const float2 bb3 = *(const float2*)(b3 + cc);
            #pragma unroll
            for (int h = 0; h < 2; h++) {
                const int rl = rloc + h * 8, i0 = h * 2;
                float z0 = tanhf(acc[0][mi][ni][i0]     + bb1.x);
                float z1 = tanhf(acc[0][mi][ni][i0 + 1] + bb1.y);
                float r0 = 1.f / (1.f + __expf(-(acc[1][mi][ni][i0]     + bb2.x)));
                float r1 = 1.f / (1.f + __expf(-(acc[1][mi][ni][i0 + 1] + bb2.y)));
                float f0 = 1.f / (1.f + __expf(-(acc[2][mi][ni][i0]     + bb3.x)));
                float f1 = 1.f / (1.f + __expf(-(acc[2][mi][ni][i0 + 1] + bb3.y)));
                const float2 xv = *(const float2*)(x + (size_t)(row0 + rl) * DD + cc);
                float2 o = make_float2(r0 * xv.x + f0 * z0, r1 * xv.y + f1 * z1);
                *(float2*)(out + (size_t)(row0 + rl) * DD + cc) = o;
            }
        }
}

// ===========================================================================
extern "C" void kernel_launch(void* const* d_in, const int* in_sizes, int n_in,
                              void* d_out, int out_size)
{
    const float* x   = (const float*)d_in[0];
    const float* wia = (const float*)d_in[1];
    const float* w1  = (const float*)d_in[2];
    const float* w2  = (const float*)d_in[3];
    const float* w3  = (const float*)d_in[4];
    const float* b1  = (const float*)d_in[5];
    const float* b2  = (const float*)d_in[6];
    const float* b3  = (const float*)d_in[7];
    float* out = (float*)d_out;

    cudaFuncSetAttribute(attn_kernel, cudaFuncAttributeMaxDynamicSharedMemorySize, A_END);
    cudaFuncSetAttribute(mlp_kernel,  cudaFuncAttributeMaxDynamicSharedMemorySize, M_END);

    prep_su  <<<LL * BB / 8, 256>>>(x, wia);
    prep_pack<<<BB * 128, 256>>>(x, wia);
    prep_w   <<<96, 256>>>(w1, w2, w3);
    attn_kernel<<<dim3(LL / BM, BB), 256, A_END>>>();
    mlp_kernel <<<dim3(BB * LL / 128, 4), 256, M_END>>>(x, b1, b2, b3, out);
}